// round 4
// baseline (speedup 1.0000x reference)
#include <cuda_runtime.h>
#include <cuda_bf16.h>
#include <cstdint>

#define SEQ   2048
#define D_IN  300
#define U     150
#define NZ    600      // 4 gates * U
#define KP    152      // padded recurrence depth (multiple of 4)
#define H1    300
#define TE    8        // timestep tile for embZ
#define TT    8        // timestep tile for outGemm

// ------------------------- scratch (static device memory; no allocs) ---------
__device__ float g_Z[2][SEQ][NZ];        // precomputed x@Wk + b, per direction
__device__ float g_hidden[SEQ][H1];      // [hf | hb] concat
__device__ float g_out[SEQ][H1];         // hidden @ W1 + b1
__device__ float g_H[H1];                // final weighted sum

// ------------------------- small PTX helpers ---------------------------------
__device__ __forceinline__ uint32_t smem_u32(const void* p) {
    return (uint32_t)__cvta_generic_to_shared(p);
}
__device__ __forceinline__ uint32_t mapa_rank(uint32_t addr, uint32_t r) {
    uint32_t out;
    asm("mapa.shared::cluster.u32 %0, %1, %2;" : "=r"(out) : "r"(addr), "r"(r));
    return out;
}
__device__ __forceinline__ void cluster_sync_() {
    asm volatile("barrier.cluster.arrive.aligned;" ::: "memory");
    asm volatile("barrier.cluster.wait.aligned;" ::: "memory");
}
__device__ __forceinline__ uint32_t my_cluster_rank() {
    uint32_t r;
    asm("mov.u32 %0, %%cluster_ctarank;" : "=r"(r));
    return r;
}
__device__ __forceinline__ unsigned long long pack2(float lo, float hi) {
    unsigned long long r;
    asm("mov.b64 %0, {%1, %2};" : "=l"(r) : "f"(lo), "f"(hi));
    return r;
}
__device__ __forceinline__ void fma2(unsigned long long& d, unsigned long long a,
                                     unsigned long long b) {
    asm("fma.rn.f32x2 %0, %1, %2, %0;" : "+l"(d) : "l"(a), "l"(b));
}
__device__ __forceinline__ void unpack2(unsigned long long v, float& lo, float& hi) {
    asm("mov.b64 {%0, %1}, %2;" : "=f"(lo), "=f"(hi) : "l"(v));
}
__device__ __forceinline__ float tanh_approx(float x) {
    float r;
    asm("tanh.approx.f32 %0, %1;" : "=f"(r) : "f"(x));
    return r;
}
__device__ __forceinline__ float sigmoid_fast(float x) {
    // 1 / (1 + 2^(-x*log2e))
    float e;
    asm("ex2.approx.f32 %0, %1;" : "=f"(e) : "f"(-1.4426950408889634f * x));
    float r;
    asm("rcp.approx.f32 %0, %1;" : "=f"(r) : "f"(1.0f + e));
    return r;
}
__device__ __forceinline__ void mbar_init(uint32_t addr, uint32_t cnt) {
    asm volatile("mbarrier.init.shared.b64 [%0], %1;" :: "r"(addr), "r"(cnt) : "memory");
}
__device__ __forceinline__ void mbar_arrive_expect_tx(uint32_t addr, uint32_t tx) {
    asm volatile("mbarrier.arrive.expect_tx.shared.b64 _, [%0], %1;"
                 :: "r"(addr), "r"(tx) : "memory");
}
__device__ __forceinline__ void mbar_wait_parity_acq_cluster(uint32_t addr, uint32_t parity) {
    asm volatile(
        "{\n\t"
        ".reg .pred P1;\n\t"
        "WAIT_LOOP_%=:\n\t"
        "mbarrier.try_wait.parity.acquire.cluster.shared::cta.b64 P1, [%0], %1, 0x989680;\n\t"
        "@P1 bra.uni WAIT_DONE_%=;\n\t"
        "bra.uni WAIT_LOOP_%=;\n\t"
        "WAIT_DONE_%=:\n\t"
        "}"
        :: "r"(addr), "r"(parity) : "memory");
}
__device__ __forceinline__ void st_async_f32(uint32_t daddr, float v, uint32_t mbar) {
    asm volatile("st.async.shared::cluster.mbarrier::complete_tx::bytes.f32 [%0], %1, [%2];"
                 :: "r"(daddr), "f"(v), "r"(mbar) : "memory");
}

// ============================================================================
// Kernel 0: zero the accumulator for H
// ============================================================================
__global__ void zeroH_kernel() {
    if (threadIdx.x < H1) g_H[threadIdx.x] = 0.f;
}

// ============================================================================
// Kernel 1: Z[dir][t][:] = x_t @ Wk + b, tiled over TE=8 timesteps so Wk is
// read from L2 only SEQ/TE times. grid (SEQ/TE, 2), block 160.
// ============================================================================
__global__ void __launch_bounds__(160) embZ_kernel(
    const int* __restrict__ sentence, const float* __restrict__ E,
    const float* __restrict__ Wk_f, const float* __restrict__ b_f,
    const float* __restrict__ Wk_b, const float* __restrict__ b_b)
{
    __shared__ float x_sh[TE][D_IN];
    const int t0  = blockIdx.x * TE;
    const int dir = blockIdx.y;

    for (int i = threadIdx.x; i < TE * D_IN; i += 160) {
        const int r = i / D_IN, d = i % D_IN;
        x_sh[r][d] = E[(size_t)sentence[t0 + r] * D_IN + d];
    }
    __syncthreads();

    const float* __restrict__ Wk = dir ? Wk_b : Wk_f;
    const float* __restrict__ b  = dir ? b_b  : b_f;

    const int j = threadIdx.x * 4;
    if (j < NZ) {
        const float4 bv = *(const float4*)(b + j);
        float4 acc[TE];
        #pragma unroll
        for (int r = 0; r < TE; r++) acc[r] = bv;

        #pragma unroll 2
        for (int d = 0; d < D_IN; d++) {
            const float4 wv = *(const float4*)(Wk + d * NZ + j);
            #pragma unroll
            for (int r = 0; r < TE; r++) {
                const float x = x_sh[r][d];
                acc[r].x = fmaf(x, wv.x, acc[r].x);
                acc[r].y = fmaf(x, wv.y, acc[r].y);
                acc[r].z = fmaf(x, wv.z, acc[r].z);
                acc[r].w = fmaf(x, wv.w, acc[r].w);
            }
        }
        #pragma unroll
        for (int r = 0; r < TE; r++)
            *(float4*)&g_Z[dir][t0 + r][j] = acc[r];
    }
}

// ============================================================================
// Kernel 2: sequential bidirectional LSTM recurrence.
// grid (4, 2), cluster (4,1,1): blockIdx.y = direction, cluster rank = gate.
// Wr gate slice register-resident as f32x2 pairs. Gate exchange uses st.async
// + double-buffered mbarriers (no cluster.sync -> no per-step L1 flush).
// ============================================================================
__global__ void __cluster_dims__(4, 1, 1) __launch_bounds__(160, 1)
lstm_rec_kernel(const float* __restrict__ Wr_f, const float* __restrict__ Wr_b)
{
    __shared__ __align__(16) float h_sh[KP];
    __shared__ __align__(16) float gates_sh[2][U][4];   // [buf][out][gate] -> float4 read
    __shared__ __align__(8)  unsigned long long mbar_sh[2];

    const int tid  = threadIdx.x;
    const uint32_t rank = my_cluster_rank();   // 0=i, 1=f, 2=g(cell), 3=o
    const int dir  = blockIdx.y;
    const float* __restrict__ Wr = dir ? Wr_b : Wr_f;

    if (tid < KP) h_sh[tid] = 0.f;
    if (tid == 0) {
        mbar_init(smem_u32(&mbar_sh[0]), 1);
        mbar_init(smem_u32(&mbar_sh[1]), 1);
    }

    // register-resident weights as f32x2: column (rank*U + tid) of Wr
    const int col = (tid < U) ? (rank * U + tid) : 0;
    unsigned long long w2[KP / 2];
    #pragma unroll
    for (int jj = 0; jj < KP / 2; jj++) {
        float wa = 0.f, wb = 0.f;
        if (tid < U) {
            const int k = 2 * jj;
            if (k     < U) wa = Wr[k * NZ + col];
            if (k + 1 < U) wb = Wr[(k + 1) * NZ + col];
        }
        w2[jj] = pack2(wa, wb);
    }

    // DSMEM addresses: my gate slot + mbarrier in all 4 cluster CTAs, both bufs
    uint32_t ga[2][4], ba[2][4];
    {
        const int tt = (tid < U) ? tid : 0;
        const uint32_t g0 = smem_u32(&gates_sh[0][tt][rank]);
        const uint32_t g1 = smem_u32(&gates_sh[1][tt][rank]);
        const uint32_t b0 = smem_u32(&mbar_sh[0]);
        const uint32_t b1 = smem_u32(&mbar_sh[1]);
        #pragma unroll
        for (uint32_t r = 0; r < 4; r++) {
            ga[0][r] = mapa_rank(g0, r);
            ga[1][r] = mapa_rank(g1, r);
            ba[0][r] = mapa_rank(b0, r);
            ba[1][r] = mapa_rank(b1, r);
        }
    }
    const uint32_t my_bar[2] = { smem_u32(&mbar_sh[0]), smem_u32(&mbar_sh[1]) };

    float c = 0.f;   // cell state, redundantly owned by tid<U in every CTA
    __syncthreads();
    cluster_sync_();   // barriers initialized cluster-wide before any st.async

    float zpre = (tid < U) ? g_Z[dir][dir ? (SEQ - 1) : 0][rank * U + tid] : 0.f;

    for (int ti = 0; ti < SEQ; ti++) {
        const int t   = dir ? (SEQ - 1 - ti) : ti;
        const int buf = ti & 1;
        const uint32_t parity = (ti >> 1) & 1;

        // consumer side: one arrive + expect 4 CTAs * 150 threads * 4B
        if (tid == 0) mbar_arrive_expect_tx(my_bar[buf], 4 * U * 4);

        // z = zpre + h . w   (f32x2 packed dot; h broadcast from shared)
        unsigned long long a0 = pack2(zpre, 0.f), a1 = pack2(0.f, 0.f);
        const ulonglong2* h2 = (const ulonglong2*)h_sh;
        #pragma unroll
        for (int k = 0; k < KP / 4; k++) {
            const ulonglong2 hv = h2[k];
            fma2(a0, hv.x, w2[2 * k + 0]);
            fma2(a1, hv.y, w2[2 * k + 1]);
        }
        float f0, f1, f2, f3;
        unpack2(a0, f0, f1);
        unpack2(a1, f2, f3);
        const float z = (f0 + f2) + (f1 + f3);

        // activation for this CTA's gate, async-store to all 4 cluster CTAs
        if (tid < U) {
            const float a = (rank == 2) ? tanh_approx(z) : sigmoid_fast(z);
            st_async_f32(ga[buf][0], a, ba[buf][0]);
            st_async_f32(ga[buf][1], a, ba[buf][1]);
            st_async_f32(ga[buf][2], a, ba[buf][2]);
            st_async_f32(ga[buf][3], a, ba[buf][3]);
        }

        // prefetch next step's Z while gates are in flight
        float zn = 0.f;
        if (ti + 1 < SEQ && tid < U) {
            const int tn = dir ? (SEQ - 2 - ti) : (ti + 1);
            zn = __ldg(&g_Z[dir][tn][rank * U + tid]);
        }

        mbar_wait_parity_acq_cluster(my_bar[buf], parity);

        if (tid < U) {
            const float4 g = *(const float4*)&gates_sh[buf][tid][0]; // i,f,g,o
            c = fmaf(g.y, c, g.x * g.z);
            const float h = g.w * tanh_approx(c);
            h_sh[tid] = h;
            if (rank == 0) g_hidden[t][dir * U + tid] = h;
        }
        __syncthreads();   // h_sh ready for next step's dot
        zpre = zn;
    }
    cluster_sync_();   // keep peers alive until all remote traffic retired
}

// ============================================================================
// Kernel 3: out = hidden @ W1 + b1, tiled over TT=8 rows per block so W1 is
// read from L2 only SEQ/TT times. grid SEQ/TT, block 320.
// ============================================================================
__global__ void __launch_bounds__(320) outGemm_kernel(
    const float* __restrict__ W1, const float* __restrict__ b1)
{
    __shared__ float hrow[TT][H1];
    const int t0 = blockIdx.x * TT;
    for (int i = threadIdx.x; i < TT * H1; i += 320)
        hrow[i / H1][i % H1] = g_hidden[t0 + i / H1][i % H1];
    __syncthreads();

    const int j = threadIdx.x;
    if (j < H1) {
        const float bj = b1[j];
        float acc[TT];
        #pragma unroll
        for (int r = 0; r < TT; r++) acc[r] = bj;
        #pragma unroll 2
        for (int d = 0; d < H1; d++) {
            const float w = W1[d * H1 + j];
            #pragma unroll
            for (int r = 0; r < TT; r++) acc[r] = fmaf(hrow[r][d], w, acc[r]);
        }
        #pragma unroll
        for (int r = 0; r < TT; r++) g_out[t0 + r][j] = acc[r];
    }
}

// ============================================================================
// Kernel 4: per-position synonym attention + h_hat + c2, accumulate H.
// grid SEQ, block 128 (warp k handles synonym k).
// ============================================================================
__global__ void __launch_bounds__(128) syn_kernel(
    const int* __restrict__ sentence, const int* __restrict__ syn,
    const float* __restrict__ E,
    const float* __restrict__ W2, const float* __restrict__ b2)
{
    __shared__ float orow[H1];
    __shared__ float hhat[H1];
    __shared__ float e_sh[4][H1];
    __shared__ float coeff_sh[4];
    __shared__ float red_sh[4];
    __shared__ float c2_sh;

    const int s    = blockIdx.x;
    const int idx  = s ? (s - 1) : 0;
    const int tid  = threadIdx.x;
    const int wid  = tid >> 5;
    const int lane = tid & 31;

    for (int d = tid; d < H1; d += 128) {
        orow[d] = g_out[idx][d];
        hhat[d] = g_hidden[idx][d];
    }
    __syncthreads();

    // warp wid: load synonym row wid, dot with orow, coeff = exp(dot)
    {
        const int tok = sentence[s];
        const float* __restrict__ e = E + (size_t)syn[tok * 4 + wid] * D_IN;
        float p = 0.f;
        for (int d = lane; d < H1; d += 32) {
            const float ev = e[d];
            e_sh[wid][d] = ev;
            p = fmaf(ev, orow[d], p);
        }
        #pragma unroll
        for (int o = 16; o > 0; o >>= 1) p += __shfl_xor_sync(0xffffffffu, p, o);
        if (lane == 0) coeff_sh[wid] = __expf(p);
    }
    __syncthreads();

    const float c0 = coeff_sh[0], c1 = coeff_sh[1], c2c = coeff_sh[2], c3 = coeff_sh[3];
    for (int d = tid; d < H1; d += 128) {
        float v = hhat[d];
        v = fmaf(c0, e_sh[0][d], v);
        v = fmaf(c1, e_sh[1][d], v);
        v = fmaf(c2c, e_sh[2][d], v);
        v = fmaf(c3, e_sh[3][d], v);
        hhat[d] = v;
    }
    __syncthreads();

    // c2 = exp(tanh(hhat . W2 + b2))
    float p = 0.f;
    for (int d = tid; d < H1; d += 128) p = fmaf(hhat[d], W2[d], p);
    #pragma unroll
    for (int o = 16; o > 0; o >>= 1) p += __shfl_xor_sync(0xffffffffu, p, o);
    if (lane == 0) red_sh[wid] = p;
    __syncthreads();
    if (tid == 0)
        c2_sh = __expf(tanhf(red_sh[0] + red_sh[1] + red_sh[2] + red_sh[3] + b2[0]));
    __syncthreads();

    const float c2 = c2_sh;
    for (int d = tid; d < H1; d += 128) atomicAdd(&g_H[d], c2 * hhat[d]);
}

// ============================================================================
// Kernel 5: heads — out[0..7] = H@We + be, out[8] = H@Ws + bs
// ============================================================================
__global__ void heads_kernel(
    const float* __restrict__ We, const float* __restrict__ be,
    const float* __restrict__ Ws, const float* __restrict__ bs,
    float* __restrict__ out)
{
    const int j = threadIdx.x;
    if (j < 8) {
        float acc = be[j];
        for (int d = 0; d < H1; d++) acc = fmaf(g_H[d], We[d * 8 + j], acc);
        out[j] = acc;
    } else if (j == 8) {
        float acc = bs[0];
        for (int d = 0; d < H1; d++) acc = fmaf(g_H[d], Ws[d], acc);
        out[8] = acc;
    }
}

// ============================================================================
extern "C" void kernel_launch(void* const* d_in, const int* in_sizes, int n_in,
                              void* d_out, int out_size)
{
    const int*   sentence = (const int*)  d_in[0];
    const int*   syn      = (const int*)  d_in[1];
    const float* E        = (const float*)d_in[2];
    const float* Wk_f     = (const float*)d_in[3];
    const float* Wr_f     = (const float*)d_in[4];
    const float* b_f      = (const float*)d_in[5];
    const float* Wk_b     = (const float*)d_in[6];
    const float* Wr_b     = (const float*)d_in[7];
    const float* b_b      = (const float*)d_in[8];
    const float* W1       = (const float*)d_in[9];
    const float* b1       = (const float*)d_in[10];
    const float* W2       = (const float*)d_in[11];
    const float* b2       = (const float*)d_in[12];
    const float* We       = (const float*)d_in[13];
    const float* be       = (const float*)d_in[14];
    const float* Ws       = (const float*)d_in[15];
    const float* bs       = (const float*)d_in[16];
    float* out = (float*)d_out;

    zeroH_kernel<<<1, 320>>>();
    embZ_kernel<<<dim3(SEQ / TE, 2), 160>>>(sentence, E, Wk_f, b_f, Wk_b, b_b);
    lstm_rec_kernel<<<dim3(4, 2), 160>>>(Wr_f, Wr_b);
    outGemm_kernel<<<SEQ / TT, 320>>>(W1, b1);
    syn_kernel<<<SEQ, 128>>>(sentence, syn, E, W2, b2);
    heads_kernel<<<1, 32>>>(We, be, Ws, bs, out);
}

// round 5
// speedup vs baseline: 1.3058x; 1.3058x over previous
#include <cuda_runtime.h>
#include <cuda_bf16.h>
#include <cstdint>

#define SEQ   2048
#define D_IN  300
#define U     150
#define NZ    600      // 4 gates * U
#define KP    152      // padded recurrence depth (multiple of 4; slot = 608B)
#define H1    300
#define TE    8        // timestep tile for embZ
#define TT    4        // timestep tile for outGemm

// ------------------------- scratch (static device memory; no allocs) ---------
__device__ float g_Z[2][SEQ][NZ];        // precomputed x@Wk + b, per direction
__device__ float g_hidden[SEQ][H1];      // [hf | hb] concat
__device__ float g_out[SEQ][H1];         // hidden @ W1 + b1
__device__ float g_H[H1];                // final weighted sum

// ------------------------- small PTX helpers ---------------------------------
__device__ __forceinline__ uint32_t smem_u32(const void* p) {
    return (uint32_t)__cvta_generic_to_shared(p);
}
__device__ __forceinline__ uint32_t mapa_rank(uint32_t addr, uint32_t r) {
    uint32_t out;
    asm("mapa.shared::cluster.u32 %0, %1, %2;" : "=r"(out) : "r"(addr), "r"(r));
    return out;
}
__device__ __forceinline__ void cluster_sync_() {
    asm volatile("barrier.cluster.arrive.aligned;" ::: "memory");
    asm volatile("barrier.cluster.wait.aligned;" ::: "memory");
}
__device__ __forceinline__ uint32_t my_cluster_rank() {
    uint32_t r;
    asm("mov.u32 %0, %%cluster_ctarank;" : "=r"(r));
    return r;
}
__device__ __forceinline__ unsigned long long pack2(float lo, float hi) {
    unsigned long long r;
    asm("mov.b64 %0, {%1, %2};" : "=l"(r) : "f"(lo), "f"(hi));
    return r;
}
__device__ __forceinline__ void fma2(unsigned long long& d, unsigned long long a,
                                     unsigned long long b) {
    asm("fma.rn.f32x2 %0, %1, %2, %0;" : "+l"(d) : "l"(a), "l"(b));
}
__device__ __forceinline__ void unpack2(unsigned long long v, float& lo, float& hi) {
    asm("mov.b64 {%0, %1}, %2;" : "=f"(lo), "=f"(hi) : "l"(v));
}
__device__ __forceinline__ float tanh_approx(float x) {
    float r;
    asm("tanh.approx.f32 %0, %1;" : "=f"(r) : "f"(x));
    return r;
}
__device__ __forceinline__ float sigmoid_fast(float x) {
    float e;
    asm("ex2.approx.f32 %0, %1;" : "=f"(e) : "f"(-1.4426950408889634f * x));
    float r;
    asm("rcp.approx.f32 %0, %1;" : "=f"(r) : "f"(1.0f + e));
    return r;
}
__device__ __forceinline__ void mbar_init(uint32_t addr, uint32_t cnt) {
    asm volatile("mbarrier.init.shared.b64 [%0], %1;" :: "r"(addr), "r"(cnt) : "memory");
}
__device__ __forceinline__ void mbar_arrive_expect_tx(uint32_t addr, uint32_t tx) {
    asm volatile("mbarrier.arrive.expect_tx.shared.b64 _, [%0], %1;"
                 :: "r"(addr), "r"(tx) : "memory");
}
// CTA-scope acquire wait — async-proxy completion (complete_tx) provides the
// cross-CTA visibility; no cluster-scope fence -> no per-step L1D flush.
__device__ __forceinline__ void mbar_wait_parity_cta(uint32_t addr, uint32_t parity) {
    asm volatile(
        "{\n\t"
        ".reg .pred P1;\n\t"
        "WAIT_LOOP_%=:\n\t"
        "mbarrier.try_wait.parity.acquire.cta.shared::cta.b64 P1, [%0], %1, 0x989680;\n\t"
        "@P1 bra.uni WAIT_DONE_%=;\n\t"
        "bra.uni WAIT_LOOP_%=;\n\t"
        "WAIT_DONE_%=:\n\t"
        "}"
        :: "r"(addr), "r"(parity) : "memory");
}
__device__ __forceinline__ void fence_proxy_async_cta() {
    asm volatile("fence.proxy.async.shared::cta;" ::: "memory");
}
// one bulk DSMEM copy, single complete_tx transaction at the remote barrier
__device__ __forceinline__ void bulk_copy_cluster(uint32_t dst, uint32_t src,
                                                  uint32_t bytes, uint32_t rbar) {
    asm volatile(
        "cp.async.bulk.shared::cluster.shared::cta.mbarrier::complete_tx::bytes "
        "[%0], [%1], %2, [%3];"
        :: "r"(dst), "r"(src), "r"(bytes), "r"(rbar) : "memory");
}

// ============================================================================
// Kernel 0: zero the accumulator for H
// ============================================================================
__global__ void zeroH_kernel() {
    if (threadIdx.x < H1) g_H[threadIdx.x] = 0.f;
}

// ============================================================================
// Kernel 1: Z[dir][t][:] = x_t @ Wk + b, tiled over TE=8 timesteps.
// grid (SEQ/TE, 2), block 160.
// ============================================================================
__global__ void __launch_bounds__(160) embZ_kernel(
    const int* __restrict__ sentence, const float* __restrict__ E,
    const float* __restrict__ Wk_f, const float* __restrict__ b_f,
    const float* __restrict__ Wk_b, const float* __restrict__ b_b)
{
    __shared__ float x_sh[TE][D_IN];
    const int t0  = blockIdx.x * TE;
    const int dir = blockIdx.y;

    for (int i = threadIdx.x; i < TE * D_IN; i += 160) {
        const int r = i / D_IN, d = i % D_IN;
        x_sh[r][d] = E[(size_t)sentence[t0 + r] * D_IN + d];
    }
    __syncthreads();

    const float* __restrict__ Wk = dir ? Wk_b : Wk_f;
    const float* __restrict__ b  = dir ? b_b  : b_f;

    const int j = threadIdx.x * 4;
    if (j < NZ) {
        const float4 bv = *(const float4*)(b + j);
        float4 acc[TE];
        #pragma unroll
        for (int r = 0; r < TE; r++) acc[r] = bv;

        #pragma unroll 2
        for (int d = 0; d < D_IN; d++) {
            const float4 wv = *(const float4*)(Wk + d * NZ + j);
            #pragma unroll
            for (int r = 0; r < TE; r++) {
                const float x = x_sh[r][d];
                acc[r].x = fmaf(x, wv.x, acc[r].x);
                acc[r].y = fmaf(x, wv.y, acc[r].y);
                acc[r].z = fmaf(x, wv.z, acc[r].z);
                acc[r].w = fmaf(x, wv.w, acc[r].w);
            }
        }
        #pragma unroll
        for (int r = 0; r < TE; r++)
            *(float4*)&g_Z[dir][t0 + r][j] = acc[r];
    }
}

// ============================================================================
// Kernel 2: sequential bidirectional LSTM recurrence.
// grid (4, 2), cluster (4,1,1): blockIdx.y = direction, cluster rank = gate.
// 320 threads: 2 threads per output (split-k halves of the 150-deep dot),
// Wr slice register-resident as f32x2 pairs. Gate exchange: one 608B bulk
// DSMEM copy per peer per step (3 tx transactions total), cta-scope waits.
// ============================================================================
__global__ void __cluster_dims__(4, 1, 1) __launch_bounds__(320, 1)
lstm_rec_kernel(const float* __restrict__ Wr_f, const float* __restrict__ Wr_b)
{
    __shared__ __align__(16) float h_sh[KP];
    __shared__ __align__(16) float gates_sh[2][4][KP];   // [buf][gate][out], 608B slots
    __shared__ __align__(8)  unsigned long long mbar_sh[2];

    const int tid  = threadIdx.x;
    const int o    = tid >> 1;          // output index 0..159
    const int kh   = tid & 1;           // k-half: 0 -> k[0..75], 1 -> k[76..151]
    const bool act = (o < U);
    const bool lead = act && (kh == 0);
    const uint32_t rank = my_cluster_rank();   // 0=i, 1=f, 2=g(cell), 3=o
    const int dir  = blockIdx.y;
    const float* __restrict__ Wr = dir ? Wr_b : Wr_f;

    if (tid < KP) h_sh[tid] = 0.f;
    if (tid == 0) {
        mbar_init(smem_u32(&mbar_sh[0]), 1);
        mbar_init(smem_u32(&mbar_sh[1]), 1);
    }

    // register-resident weights (my k-half of column rank*U+o), f32x2 packed
    const int col = act ? (rank * U + o) : 0;
    unsigned long long w2[38];
    #pragma unroll
    for (int jj = 0; jj < 38; jj++) {
        const int k = kh * 76 + 2 * jj;
        float wa = 0.f, wb = 0.f;
        if (act && k     < U) wa = Wr[k * NZ + col];
        if (act && k + 1 < U) wb = Wr[(k + 1) * NZ + col];
        w2[jj] = pack2(wa, wb);
    }

    // DSMEM targets (for the elected copier): my gate slot + barrier in peers
    uint32_t dstA[2][3], barA[2][3];
    {
        int n = 0;
        const uint32_t s0 = smem_u32(&gates_sh[0][rank][0]);
        const uint32_t s1 = smem_u32(&gates_sh[1][rank][0]);
        const uint32_t b0 = smem_u32(&mbar_sh[0]);
        const uint32_t b1 = smem_u32(&mbar_sh[1]);
        for (uint32_t r = 0; r < 4; r++) {
            if (r == rank) continue;
            dstA[0][n] = mapa_rank(s0, r);
            dstA[1][n] = mapa_rank(s1, r);
            barA[0][n] = mapa_rank(b0, r);
            barA[1][n] = mapa_rank(b1, r);
            n++;
        }
    }
    const uint32_t srcA[2]   = { smem_u32(&gates_sh[0][rank][0]),
                                 smem_u32(&gates_sh[1][rank][0]) };
    const uint32_t my_bar[2] = { smem_u32(&mbar_sh[0]), smem_u32(&mbar_sh[1]) };

    float c = 0.f;   // cell state (lead threads), redundant in every CTA
    __syncthreads();
    cluster_sync_();   // barriers live cluster-wide before any bulk copy

    float zpre = lead ? g_Z[dir][dir ? (SEQ - 1) : 0][rank * U + o] : 0.f;

    for (int ti = 0; ti < SEQ; ti++) {
        const int t   = dir ? (SEQ - 1 - ti) : ti;
        const int buf = ti & 1;
        const uint32_t parity = (ti >> 1) & 1;

        // half-dot: 38 packed FMAs over my k-half of h
        unsigned long long acc = pack2(zpre, 0.f);
        const unsigned long long* hp =
            (const unsigned long long*)(h_sh + kh * 76);
        #pragma unroll
        for (int j = 0; j < 38; j++) fma2(acc, hp[j], w2[j]);
        float lo, hi;
        unpack2(acc, lo, hi);
        float z = lo + hi;
        z += __shfl_xor_sync(0xffffffffu, z, 1);   // combine the two k-halves

        // activation, written into the local slot for my gate
        if (lead) {
            const float a = (rank == 2) ? tanh_approx(z) : sigmoid_fast(z);
            gates_sh[buf][rank][o] = a;
        }
        __syncthreads();   // slot complete before async-proxy reads it

        if (tid == 0) {
            fence_proxy_async_cta();                    // STS -> async-proxy read
            mbar_arrive_expect_tx(my_bar[buf], 3 * 608);
            bulk_copy_cluster(dstA[buf][0], srcA[buf], 608, barA[buf][0]);
            bulk_copy_cluster(dstA[buf][1], srcA[buf], 608, barA[buf][1]);
            bulk_copy_cluster(dstA[buf][2], srcA[buf], 608, barA[buf][2]);
        }

        // prefetch next step's Z while copies are in flight
        float zn = 0.f;
        if (lead && ti + 1 < SEQ)
            zn = __ldg(&g_Z[dir][dir ? (SEQ - 2 - ti) : (ti + 1)][rank * U + o]);

        mbar_wait_parity_cta(my_bar[buf], parity);

        if (lead) {
            const float gi = gates_sh[buf][0][o];
            const float gf = gates_sh[buf][1][o];
            const float gg = gates_sh[buf][2][o];
            const float go = gates_sh[buf][3][o];
            c = fmaf(gf, c, gi * gg);
            const float h = go * tanh_approx(c);
            h_sh[o] = h;
            if (rank == 0) g_hidden[t][dir * U + o] = h;
        }
        __syncthreads();   // h_sh ready for next step's dot
        zpre = zn;
    }
    cluster_sync_();   // keep peers alive until all remote traffic retired
}

// ============================================================================
// Kernel 3: out = hidden @ W1 + b1, TT=4 rows per block (grid 512 -> occ up).
// ============================================================================
__global__ void __launch_bounds__(320) outGemm_kernel(
    const float* __restrict__ W1, const float* __restrict__ b1)
{
    __shared__ float hrow[TT][H1];
    const int t0 = blockIdx.x * TT;
    for (int i = threadIdx.x; i < TT * H1; i += 320)
        hrow[i / H1][i % H1] = g_hidden[t0 + i / H1][i % H1];
    __syncthreads();

    const int j = threadIdx.x;
    if (j < H1) {
        const float bj = b1[j];
        float acc[TT];
        #pragma unroll
        for (int r = 0; r < TT; r++) acc[r] = bj;
        #pragma unroll 4
        for (int d = 0; d < H1; d++) {
            const float w = __ldg(&W1[d * H1 + j]);
            #pragma unroll
            for (int r = 0; r < TT; r++) acc[r] = fmaf(hrow[r][d], w, acc[r]);
        }
        #pragma unroll
        for (int r = 0; r < TT; r++) g_out[t0 + r][j] = acc[r];
    }
}

// ============================================================================
// Kernel 4: per-position synonym attention + h_hat + c2, accumulate H.
// grid SEQ, block 128 (warp k handles synonym k).
// ============================================================================
__global__ void __launch_bounds__(128) syn_kernel(
    const int* __restrict__ sentence, const int* __restrict__ syn,
    const float* __restrict__ E,
    const float* __restrict__ W2, const float* __restrict__ b2)
{
    __shared__ float orow[H1];
    __shared__ float hhat[H1];
    __shared__ float e_sh[4][H1];
    __shared__ float coeff_sh[4];
    __shared__ float red_sh[4];
    __shared__ float c2_sh;

    const int s    = blockIdx.x;
    const int idx  = s ? (s - 1) : 0;
    const int tid  = threadIdx.x;
    const int wid  = tid >> 5;
    const int lane = tid & 31;

    for (int d = tid; d < H1; d += 128) {
        orow[d] = g_out[idx][d];
        hhat[d] = g_hidden[idx][d];
    }
    __syncthreads();

    {
        const int tok = sentence[s];
        const float* __restrict__ e = E + (size_t)syn[tok * 4 + wid] * D_IN;
        float p = 0.f;
        for (int d = lane; d < H1; d += 32) {
            const float ev = e[d];
            e_sh[wid][d] = ev;
            p = fmaf(ev, orow[d], p);
        }
        #pragma unroll
        for (int o = 16; o > 0; o >>= 1) p += __shfl_xor_sync(0xffffffffu, p, o);
        if (lane == 0) coeff_sh[wid] = __expf(p);
    }
    __syncthreads();

    const float c0 = coeff_sh[0], c1 = coeff_sh[1], c2c = coeff_sh[2], c3 = coeff_sh[3];
    for (int d = tid; d < H1; d += 128) {
        float v = hhat[d];
        v = fmaf(c0, e_sh[0][d], v);
        v = fmaf(c1, e_sh[1][d], v);
        v = fmaf(c2c, e_sh[2][d], v);
        v = fmaf(c3, e_sh[3][d], v);
        hhat[d] = v;
    }
    __syncthreads();

    float p = 0.f;
    for (int d = tid; d < H1; d += 128) p = fmaf(hhat[d], W2[d], p);
    #pragma unroll
    for (int o = 16; o > 0; o >>= 1) p += __shfl_xor_sync(0xffffffffu, p, o);
    if (lane == 0) red_sh[wid] = p;
    __syncthreads();
    if (tid == 0)
        c2_sh = __expf(tanhf(red_sh[0] + red_sh[1] + red_sh[2] + red_sh[3] + b2[0]));
    __syncthreads();

    const float c2 = c2_sh;
    for (int d = tid; d < H1; d += 128) atomicAdd(&g_H[d], c2 * hhat[d]);
}

// ============================================================================
// Kernel 5: heads — out[0..7] = H@We + be, out[8] = H@Ws + bs
// ============================================================================
__global__ void heads_kernel(
    const float* __restrict__ We, const float* __restrict__ be,
    const float* __restrict__ Ws, const float* __restrict__ bs,
    float* __restrict__ out)
{
    const int j = threadIdx.x;
    if (j < 8) {
        float acc = be[j];
        for (int d = 0; d < H1; d++) acc = fmaf(g_H[d], We[d * 8 + j], acc);
        out[j] = acc;
    } else if (j == 8) {
        float acc = bs[0];
        for (int d = 0; d < H1; d++) acc = fmaf(g_H[d], Ws[d], acc);
        out[8] = acc;
    }
}

// ============================================================================
extern "C" void kernel_launch(void* const* d_in, const int* in_sizes, int n_in,
                              void* d_out, int out_size)
{
    const int*   sentence = (const int*)  d_in[0];
    const int*   syn      = (const int*)  d_in[1];
    const float* E        = (const float*)d_in[2];
    const float* Wk_f     = (const float*)d_in[3];
    const float* Wr_f     = (const float*)d_in[4];
    const float* b_f      = (const float*)d_in[5];
    const float* Wk_b     = (const float*)d_in[6];
    const float* Wr_b     = (const float*)d_in[7];
    const float* b_b      = (const float*)d_in[8];
    const float* W1       = (const float*)d_in[9];
    const float* b1       = (const float*)d_in[10];
    const float* W2       = (const float*)d_in[11];
    const float* b2       = (const float*)d_in[12];
    const float* We       = (const float*)d_in[13];
    const float* be       = (const float*)d_in[14];
    const float* Ws       = (const float*)d_in[15];
    const float* bs       = (const float*)d_in[16];
    float* out = (float*)d_out;

    zeroH_kernel<<<1, 320>>>();
    embZ_kernel<<<dim3(SEQ / TE, 2), 160>>>(sentence, E, Wk_f, b_f, Wk_b, b_b);
    lstm_rec_kernel<<<dim3(4, 2), 320>>>(Wr_f, Wr_b);
    outGemm_kernel<<<SEQ / TT, 320>>>(W1, b1);
    syn_kernel<<<SEQ, 128>>>(sentence, syn, E, W2, b2);
    heads_kernel<<<1, 32>>>(We, be, Ws, bs, out);
}

// round 6
// speedup vs baseline: 1.3999x; 1.0720x over previous
#include <cuda_runtime.h>
#include <cuda_bf16.h>
#include <cstdint>

#define SEQ   2048
#define D_IN  300
#define U     150
#define NZ    600      // 4 gates * U
#define KP    152      // padded recurrence depth (multiple of 8)
#define H1    300
#define TE    8        // timestep tile for embZ
#define TT    4        // timestep tile for outGemm

// ------------------------- scratch (static device memory; no allocs) ---------
__device__ float g_Z[2][SEQ][NZ];        // precomputed x@Wk + b, per direction
__device__ float g_hidden[SEQ][H1];      // [hf | hb] concat
__device__ float g_out[SEQ][H1];         // hidden @ W1 + b1
__device__ float g_H[H1];                // final weighted sum

// ------------------------- small PTX helpers ---------------------------------
__device__ __forceinline__ uint32_t smem_u32(const void* p) {
    return (uint32_t)__cvta_generic_to_shared(p);
}
__device__ __forceinline__ uint32_t mapa_rank(uint32_t addr, uint32_t r) {
    uint32_t out;
    asm("mapa.shared::cluster.u32 %0, %1, %2;" : "=r"(out) : "r"(addr), "r"(r));
    return out;
}
__device__ __forceinline__ void cluster_sync_() {
    asm volatile("barrier.cluster.arrive.aligned;" ::: "memory");
    asm volatile("barrier.cluster.wait.aligned;" ::: "memory");
}
__device__ __forceinline__ uint32_t my_cluster_rank() {
    uint32_t r;
    asm("mov.u32 %0, %%cluster_ctarank;" : "=r"(r));
    return r;
}
__device__ __forceinline__ unsigned long long pack2(float lo, float hi) {
    unsigned long long r;
    asm("mov.b64 %0, {%1, %2};" : "=l"(r) : "f"(lo), "f"(hi));
    return r;
}
__device__ __forceinline__ void fma2(unsigned long long& d, unsigned long long a,
                                     unsigned long long b) {
    asm("fma.rn.f32x2 %0, %1, %2, %0;" : "+l"(d) : "l"(a), "l"(b));
}
__device__ __forceinline__ void unpack2(unsigned long long v, float& lo, float& hi) {
    asm("mov.b64 {%0, %1}, %2;" : "=f"(lo), "=f"(hi) : "l"(v));
}
__device__ __forceinline__ float tanh_approx(float x) {
    float r;
    asm("tanh.approx.f32 %0, %1;" : "=f"(r) : "f"(x));
    return r;
}
__device__ __forceinline__ float sigmoid_fast(float x) {
    float e;
    asm("ex2.approx.f32 %0, %1;" : "=f"(e) : "f"(-1.4426950408889634f * x));
    float r;
    asm("rcp.approx.f32 %0, %1;" : "=f"(r) : "f"(1.0f + e));
    return r;
}
__device__ __forceinline__ void mbar_init(uint32_t addr, uint32_t cnt) {
    asm volatile("mbarrier.init.shared.b64 [%0], %1;" :: "r"(addr), "r"(cnt) : "memory");
}
__device__ __forceinline__ void mbar_arrive_expect_tx(uint32_t addr, uint32_t tx) {
    asm volatile("mbarrier.arrive.expect_tx.shared.b64 _, [%0], %1;"
                 :: "r"(addr), "r"(tx) : "memory");
}
// CTA-scope acquire wait — st.async completion (complete_tx) provides the
// cross-CTA visibility; no cluster-scope fence -> no per-step L1D flush.
__device__ __forceinline__ void mbar_wait_parity_cta(uint32_t addr, uint32_t parity) {
    asm volatile(
        "{\n\t"
        ".reg .pred P1;\n\t"
        "WAIT_LOOP_%=:\n\t"
        "mbarrier.try_wait.parity.acquire.cta.shared::cta.b64 P1, [%0], %1, 0x989680;\n\t"
        "@P1 bra.uni WAIT_DONE_%=;\n\t"
        "bra.uni WAIT_LOOP_%=;\n\t"
        "WAIT_DONE_%=:\n\t"
        "}"
        :: "r"(addr), "r"(parity) : "memory");
}
__device__ __forceinline__ void st_async_f32(uint32_t daddr, float v, uint32_t mbar) {
    asm volatile("st.async.shared::cluster.mbarrier::complete_tx::bytes.f32 [%0], %1, [%2];"
                 :: "r"(daddr), "f"(v), "r"(mbar) : "memory");
}

// ============================================================================
// Kernel 0: zero the accumulator for H
// ============================================================================
__global__ void zeroH_kernel() {
    if (threadIdx.x < H1) g_H[threadIdx.x] = 0.f;
}

// ============================================================================
// Kernel 1: Z[dir][t][:] = x_t @ Wk + b, tiled over TE=8 timesteps.
// grid (SEQ/TE, 2), block 160.
// ============================================================================
__global__ void __launch_bounds__(160) embZ_kernel(
    const int* __restrict__ sentence, const float* __restrict__ E,
    const float* __restrict__ Wk_f, const float* __restrict__ b_f,
    const float* __restrict__ Wk_b, const float* __restrict__ b_b)
{
    __shared__ float x_sh[TE][D_IN];
    const int t0  = blockIdx.x * TE;
    const int dir = blockIdx.y;

    for (int i = threadIdx.x; i < TE * D_IN; i += 160) {
        const int r = i / D_IN, d = i % D_IN;
        x_sh[r][d] = E[(size_t)sentence[t0 + r] * D_IN + d];
    }
    __syncthreads();

    const float* __restrict__ Wk = dir ? Wk_b : Wk_f;
    const float* __restrict__ b  = dir ? b_b  : b_f;

    const int j = threadIdx.x * 4;
    if (j < NZ) {
        const float4 bv = *(const float4*)(b + j);
        float4 acc[TE];
        #pragma unroll
        for (int r = 0; r < TE; r++) acc[r] = bv;

        #pragma unroll 2
        for (int d = 0; d < D_IN; d++) {
            const float4 wv = *(const float4*)(Wk + d * NZ + j);
            #pragma unroll
            for (int r = 0; r < TE; r++) {
                const float x = x_sh[r][d];
                acc[r].x = fmaf(x, wv.x, acc[r].x);
                acc[r].y = fmaf(x, wv.y, acc[r].y);
                acc[r].z = fmaf(x, wv.z, acc[r].z);
                acc[r].w = fmaf(x, wv.w, acc[r].w);
            }
        }
        #pragma unroll
        for (int r = 0; r < TE; r++)
            *(float4*)&g_Z[dir][t0 + r][j] = acc[r];
    }
}

// ============================================================================
// Kernel 2: sequential bidirectional LSTM recurrence — OUTPUT-SLICED.
// grid (4, 2), cluster (4,1,1): blockIdx.y = direction.
// CTA rank r owns h-outputs [r*38, min(r*38+38,150)) for ALL 4 gates:
//   - each step it computes 4 gate dots per owned output (split-k, 2 thr/dot)
//   - cell update is CTA-LOCAL (single exchange stage per step)
//   - it pushes its h-slice (<=38 floats) to the 3 peers via st.async.b32
//     into the peers' double-buffered h_sh + per-buffer mbarrier.
// ============================================================================
__global__ void __cluster_dims__(4, 1, 1) __launch_bounds__(320, 1)
lstm_rec_kernel(const float* __restrict__ Wr_f, const float* __restrict__ Wr_b)
{
    __shared__ __align__(16) float h_sh[2][KP];     // double-buffered hidden state
    __shared__ __align__(16) float a_sh[40 * 4];    // activated gates [o][g]
    __shared__ __align__(8)  unsigned long long mbar_sh[2];

    const int tid = threadIdx.x;
    const int u   = tid >> 1;          // unit 0..159 (152 real)
    const int kh  = tid & 1;           // k-half: 0 -> k[0..75], 1 -> k[76..151]
    const int g   = u & 3;             // gate 0=i 1=f 2=g 3=o
    const int o   = u >> 2;            // local output 0..39
    const uint32_t rank = my_cluster_rank();
    const int obase = rank * 38;
    const int myo   = obase + o;       // global output index
    const bool unit_act = (u < 152) && (myo < U);
    const bool lead  = unit_act && (kh == 0);
    const bool cellT = lead && (g == 0);
    const int dir = blockIdx.y;
    const float* __restrict__ Wr = dir ? Wr_b : Wr_f;
    const int col = unit_act ? (g * U + myo) : 0;
    const int mysz = (rank == 3) ? (U - 3 * 38) : 38;          // 36 or 38
    const uint32_t inbytes = (U - mysz) * 4;                   // incoming per step

    if (tid < KP) { h_sh[0][tid] = 0.f; h_sh[1][tid] = 0.f; }
    if (tid == 0) {
        mbar_init(smem_u32(&mbar_sh[0]), 1);
        mbar_init(smem_u32(&mbar_sh[1]), 1);
    }

    // register-resident weights (my k-half of Wr column `col`), f32x2 packed
    unsigned long long w2[38];
    #pragma unroll
    for (int jj = 0; jj < 38; jj++) {
        const int k = kh * 76 + 2 * jj;
        float wa = 0.f, wb = 0.f;
        if (unit_act && k     < U) wa = Wr[k * NZ + col];
        if (unit_act && k + 1 < U) wb = Wr[(k + 1) * NZ + col];
        w2[jj] = pack2(wa, wb);
    }

    // DSMEM targets for the cell threads: peer h_sh slot + mbarrier, both bufs
    uint32_t hdst[2][3], bdst[2][3];
    {
        const int oo = cellT ? myo : 0;
        const uint32_t l0 = smem_u32(&h_sh[0][oo]);
        const uint32_t l1 = smem_u32(&h_sh[1][oo]);
        const uint32_t b0 = smem_u32(&mbar_sh[0]);
        const uint32_t b1 = smem_u32(&mbar_sh[1]);
        int n = 0;
        for (uint32_t r = 0; r < 4; r++) {
            if (r == rank) continue;
            hdst[0][n] = mapa_rank(l0, r);
            hdst[1][n] = mapa_rank(l1, r);
            bdst[0][n] = mapa_rank(b0, r);
            bdst[1][n] = mapa_rank(b1, r);
            n++;
        }
    }
    const uint32_t my_bar[2] = { smem_u32(&mbar_sh[0]), smem_u32(&mbar_sh[1]) };

    float c = 0.f;                 // cell state (cell threads only)
    int par[2] = { 0, 0 };         // phase parity per barrier
    __syncthreads();
    cluster_sync_();               // barriers + zeroed h live cluster-wide

    float zpre = lead ? __ldg(&g_Z[dir][dir ? (SEQ - 1) : 0][col]) : 0.f;

    for (int ti = 0; ti < SEQ; ti++) {
        const int t  = dir ? (SEQ - 1 - ti) : ti;
        const int b  = ti & 1;
        const int nb = b ^ 1;

        // wait for the 3 peer slices of this step's h (skip t=0: h=0)
        if (ti > 0) { mbar_wait_parity_cta(my_bar[b], par[b]); par[b] ^= 1; }
        // prime next step's barrier (counter math tolerates早 stores)
        if (tid == 0 && ti + 1 < SEQ) mbar_arrive_expect_tx(my_bar[nb], inbytes);

        // z = zpre + (my k-half of h) . w    — dual accumulators
        unsigned long long a0 = pack2(zpre, 0.f), a1 = pack2(0.f, 0.f);
        const float4* h4 = (const float4*)&h_sh[b][kh * 76];
        #pragma unroll
        for (int j = 0; j < 19; j++) {
            const float4 hv = h4[j];
            fma2(a0, pack2(hv.x, hv.y), w2[2 * j + 0]);
            fma2(a1, pack2(hv.z, hv.w), w2[2 * j + 1]);
        }
        float f0, f1, f2, f3;
        unpack2(a0, f0, f1);
        unpack2(a1, f2, f3);
        float z = (f0 + f2) + (f1 + f3);
        z += __shfl_xor_sync(0xffffffffu, z, 1);    // combine k-halves

        if (lead) {
            const float a = (g == 2) ? tanh_approx(z) : sigmoid_fast(z);
            a_sh[o * 4 + g] = a;
        }
        __syncthreads();           // gates of my slice complete

        // prefetch next step's Z while exchange is in flight
        float zn = 0.f;
        if (lead && ti + 1 < SEQ)
            zn = __ldg(&g_Z[dir][dir ? (SEQ - 2 - ti) : (ti + 1)][col]);

        if (cellT) {
            const float4 av = *(const float4*)&a_sh[o * 4];   // i,f,g,o
            c = fmaf(av.y, c, av.x * av.z);
            const float h = av.w * tanh_approx(c);
            h_sh[nb][myo] = h;                    // own slice, local
            g_hidden[t][dir * U + myo] = h;
            if (ti + 1 < SEQ) {                   // push slice to 3 peers
                st_async_f32(hdst[nb][0], h, bdst[nb][0]);
                st_async_f32(hdst[nb][1], h, bdst[nb][1]);
                st_async_f32(hdst[nb][2], h, bdst[nb][2]);
            }
        }
        __syncthreads();           // own slice visible; a_sh reusable
        zpre = zn;
    }
    cluster_sync_();               // keep peers alive until traffic retired
}

// ============================================================================
// Kernel 3: out = hidden @ W1 + b1, TT=4 rows per block.
// ============================================================================
__global__ void __launch_bounds__(320) outGemm_kernel(
    const float* __restrict__ W1, const float* __restrict__ b1)
{
    __shared__ float hrow[TT][H1];
    const int t0 = blockIdx.x * TT;
    for (int i = threadIdx.x; i < TT * H1; i += 320)
        hrow[i / H1][i % H1] = g_hidden[t0 + i / H1][i % H1];
    __syncthreads();

    const int j = threadIdx.x;
    if (j < H1) {
        const float bj = b1[j];
        float acc[TT];
        #pragma unroll
        for (int r = 0; r < TT; r++) acc[r] = bj;
        #pragma unroll 4
        for (int d = 0; d < H1; d++) {
            const float w = __ldg(&W1[d * H1 + j]);
            #pragma unroll
            for (int r = 0; r < TT; r++) acc[r] = fmaf(hrow[r][d], w, acc[r]);
        }
        #pragma unroll
        for (int r = 0; r < TT; r++) g_out[t0 + r][j] = acc[r];
    }
}

// ============================================================================
// Kernel 4: per-position synonym attention + h_hat + c2, accumulate H.
// grid SEQ, block 128 (warp k handles synonym k).
// ============================================================================
__global__ void __launch_bounds__(128) syn_kernel(
    const int* __restrict__ sentence, const int* __restrict__ syn,
    const float* __restrict__ E,
    const float* __restrict__ W2, const float* __restrict__ b2)
{
    __shared__ float orow[H1];
    __shared__ float hhat[H1];
    __shared__ float e_sh[4][H1];
    __shared__ float coeff_sh[4];
    __shared__ float red_sh[4];
    __shared__ float c2_sh;

    const int s    = blockIdx.x;
    const int idx  = s ? (s - 1) : 0;
    const int tid  = threadIdx.x;
    const int wid  = tid >> 5;
    const int lane = tid & 31;

    for (int d = tid; d < H1; d += 128) {
        orow[d] = g_out[idx][d];
        hhat[d] = g_hidden[idx][d];
    }
    __syncthreads();

    {
        const int tok = sentence[s];
        const float* __restrict__ e = E + (size_t)syn[tok * 4 + wid] * D_IN;
        float p = 0.f;
        for (int d = lane; d < H1; d += 32) {
            const float ev = e[d];
            e_sh[wid][d] = ev;
            p = fmaf(ev, orow[d], p);
        }
        #pragma unroll
        for (int o = 16; o > 0; o >>= 1) p += __shfl_xor_sync(0xffffffffu, p, o);
        if (lane == 0) coeff_sh[wid] = __expf(p);
    }
    __syncthreads();

    const float c0 = coeff_sh[0], c1 = coeff_sh[1], c2c = coeff_sh[2], c3 = coeff_sh[3];
    for (int d = tid; d < H1; d += 128) {
        float v = hhat[d];
        v = fmaf(c0, e_sh[0][d], v);
        v = fmaf(c1, e_sh[1][d], v);
        v = fmaf(c2c, e_sh[2][d], v);
        v = fmaf(c3, e_sh[3][d], v);
        hhat[d] = v;
    }
    __syncthreads();

    float p = 0.f;
    for (int d = tid; d < H1; d += 128) p = fmaf(hhat[d], W2[d], p);
    #pragma unroll
    for (int o = 16; o > 0; o >>= 1) p += __shfl_xor_sync(0xffffffffu, p, o);
    if (lane == 0) red_sh[wid] = p;
    __syncthreads();
    if (tid == 0)
        c2_sh = __expf(tanhf(red_sh[0] + red_sh[1] + red_sh[2] + red_sh[3] + b2[0]));
    __syncthreads();

    const float c2 = c2_sh;
    for (int d = tid; d < H1; d += 128) atomicAdd(&g_H[d], c2 * hhat[d]);
}

// ============================================================================
// Kernel 5: heads — out[0..7] = H@We + be, out[8] = H@Ws + bs
// ============================================================================
__global__ void heads_kernel(
    const float* __restrict__ We, const float* __restrict__ be,
    const float* __restrict__ Ws, const float* __restrict__ bs,
    float* __restrict__ out)
{
    const int j = threadIdx.x;
    if (j < 8) {
        float acc = be[j];
        for (int d = 0; d < H1; d++) acc = fmaf(g_H[d], We[d * 8 + j], acc);
        out[j] = acc;
    } else if (j == 8) {
        float acc = bs[0];
        for (int d = 0; d < H1; d++) acc = fmaf(g_H[d], Ws[d], acc);
        out[8] = acc;
    }
}

// ============================================================================
extern "C" void kernel_launch(void* const* d_in, const int* in_sizes, int n_in,
                              void* d_out, int out_size)
{
    const int*   sentence = (const int*)  d_in[0];
    const int*   syn      = (const int*)  d_in[1];
    const float* E        = (const float*)d_in[2];
    const float* Wk_f     = (const float*)d_in[3];
    const float* Wr_f     = (const float*)d_in[4];
    const float* b_f      = (const float*)d_in[5];
    const float* Wk_b     = (const float*)d_in[6];
    const float* Wr_b     = (const float*)d_in[7];
    const float* b_b      = (const float*)d_in[8];
    const float* W1       = (const float*)d_in[9];
    const float* b1       = (const float*)d_in[10];
    const float* W2       = (const float*)d_in[11];
    const float* b2       = (const float*)d_in[12];
    const float* We       = (const float*)d_in[13];
    const float* be       = (const float*)d_in[14];
    const float* Ws       = (const float*)d_in[15];
    const float* bs       = (const float*)d_in[16];
    float* out = (float*)d_out;

    zeroH_kernel<<<1, 320>>>();
    embZ_kernel<<<dim3(SEQ / TE, 2), 160>>>(sentence, E, Wk_f, b_f, Wk_b, b_b);
    lstm_rec_kernel<<<dim3(4, 2), 320>>>(Wr_f, Wr_b);
    outGemm_kernel<<<SEQ / TT, 320>>>(W1, b1);
    syn_kernel<<<SEQ, 128>>>(sentence, syn, E, W2, b2);
    heads_kernel<<<1, 32>>>(We, be, Ws, bs, out);
}

// round 7
// speedup vs baseline: 1.4280x; 1.0201x over previous
#include <cuda_runtime.h>
#include <cuda_bf16.h>
#include <cstdint>

#define SEQ   2048
#define D_IN  300
#define U     150
#define NZ    600      // 4 gates * U
#define KP    152      // padded recurrence depth (multiple of 8)
#define H1    300
#define TE    8        // timestep tile for embZ
#define TT    4        // timestep tile for outGemm
#define SLICE 40       // h-outputs owned per CTA rank (rank3: 30 real + 2 pad)

// ------------------------- scratch (static device memory; no allocs) ---------
__device__ float g_Z[2][SEQ][NZ];        // precomputed x@Wk + b, per direction
__device__ float g_hidden[SEQ][H1];      // [hf | hb] concat
__device__ float g_out[SEQ][H1];         // hidden @ W1 + b1
__device__ float g_H[H1];                // final weighted sum

// ------------------------- small PTX helpers ---------------------------------
__device__ __forceinline__ uint32_t smem_u32(const void* p) {
    return (uint32_t)__cvta_generic_to_shared(p);
}
__device__ __forceinline__ uint32_t mapa_rank(uint32_t addr, uint32_t r) {
    uint32_t out;
    asm("mapa.shared::cluster.u32 %0, %1, %2;" : "=r"(out) : "r"(addr), "r"(r));
    return out;
}
__device__ __forceinline__ void cluster_sync_() {
    asm volatile("barrier.cluster.arrive.aligned;" ::: "memory");
    asm volatile("barrier.cluster.wait.aligned;" ::: "memory");
}
__device__ __forceinline__ uint32_t my_cluster_rank() {
    uint32_t r;
    asm("mov.u32 %0, %%cluster_ctarank;" : "=r"(r));
    return r;
}
__device__ __forceinline__ unsigned long long pack2(float lo, float hi) {
    unsigned long long r;
    asm("mov.b64 %0, {%1, %2};" : "=l"(r) : "f"(lo), "f"(hi));
    return r;
}
__device__ __forceinline__ void fma2(unsigned long long& d, unsigned long long a,
                                     unsigned long long b) {
    asm("fma.rn.f32x2 %0, %1, %2, %0;" : "+l"(d) : "l"(a), "l"(b));
}
__device__ __forceinline__ void unpack2(unsigned long long v, float& lo, float& hi) {
    asm("mov.b64 {%0, %1}, %2;" : "=f"(lo), "=f"(hi) : "l"(v));
}
__device__ __forceinline__ float tanh_approx(float x) {
    float r;
    asm("tanh.approx.f32 %0, %1;" : "=f"(r) : "f"(x));
    return r;
}
__device__ __forceinline__ float sigmoid_fast(float x) {
    float e;
    asm("ex2.approx.f32 %0, %1;" : "=f"(e) : "f"(-1.4426950408889634f * x));
    float r;
    asm("rcp.approx.f32 %0, %1;" : "=f"(r) : "f"(1.0f + e));
    return r;
}
__device__ __forceinline__ void mbar_init(uint32_t addr, uint32_t cnt) {
    asm volatile("mbarrier.init.shared.b64 [%0], %1;" :: "r"(addr), "r"(cnt) : "memory");
}
__device__ __forceinline__ void mbar_arrive_expect_tx(uint32_t addr, uint32_t tx) {
    asm volatile("mbarrier.arrive.expect_tx.shared.b64 _, [%0], %1;"
                 :: "r"(addr), "r"(tx) : "memory");
}
// CTA-scope acquire wait — st.async completion (complete_tx) provides the
// cross-CTA visibility; no cluster-scope fence -> no per-step L1D flush.
__device__ __forceinline__ void mbar_wait_parity_cta(uint32_t addr, uint32_t parity) {
    asm volatile(
        "{\n\t"
        ".reg .pred P1;\n\t"
        "WAIT_LOOP_%=:\n\t"
        "mbarrier.try_wait.parity.acquire.cta.shared::cta.b64 P1, [%0], %1, 0x989680;\n\t"
        "@P1 bra.uni WAIT_DONE_%=;\n\t"
        "bra.uni WAIT_LOOP_%=;\n\t"
        "WAIT_DONE_%=:\n\t"
        "}"
        :: "r"(addr), "r"(parity) : "memory");
}
// one 16-byte vector store, ONE complete_tx transaction at the remote barrier
__device__ __forceinline__ void st_async_v4(uint32_t daddr, float x, float y,
                                            float z, float w, uint32_t mbar) {
    asm volatile(
        "st.async.shared::cluster.mbarrier::complete_tx::bytes.v4.b32 "
        "[%0], {%1, %2, %3, %4}, [%5];"
        :: "r"(daddr), "f"(x), "f"(y), "f"(z), "f"(w), "r"(mbar) : "memory");
}

// ============================================================================
// Kernel 0: zero the accumulator for H
// ============================================================================
__global__ void zeroH_kernel() {
    if (threadIdx.x < H1) g_H[threadIdx.x] = 0.f;
}

// ============================================================================
// Kernel 1: Z[dir][t][:] = x_t @ Wk + b, tiled over TE=8 timesteps.
// grid (SEQ/TE, 2), block 160.
// ============================================================================
__global__ void __launch_bounds__(160) embZ_kernel(
    const int* __restrict__ sentence, const float* __restrict__ E,
    const float* __restrict__ Wk_f, const float* __restrict__ b_f,
    const float* __restrict__ Wk_b, const float* __restrict__ b_b)
{
    __shared__ float x_sh[TE][D_IN];
    const int t0  = blockIdx.x * TE;
    const int dir = blockIdx.y;

    for (int i = threadIdx.x; i < TE * D_IN; i += 160) {
        const int r = i / D_IN, d = i % D_IN;
        x_sh[r][d] = E[(size_t)sentence[t0 + r] * D_IN + d];
    }
    __syncthreads();

    const float* __restrict__ Wk = dir ? Wk_b : Wk_f;
    const float* __restrict__ b  = dir ? b_b  : b_f;

    const int j = threadIdx.x * 4;
    if (j < NZ) {
        const float4 bv = *(const float4*)(b + j);
        float4 acc[TE];
        #pragma unroll
        for (int r = 0; r < TE; r++) acc[r] = bv;

        #pragma unroll 2
        for (int d = 0; d < D_IN; d++) {
            const float4 wv = *(const float4*)(Wk + d * NZ + j);
            #pragma unroll
            for (int r = 0; r < TE; r++) {
                const float x = x_sh[r][d];
                acc[r].x = fmaf(x, wv.x, acc[r].x);
                acc[r].y = fmaf(x, wv.y, acc[r].y);
                acc[r].z = fmaf(x, wv.z, acc[r].z);
                acc[r].w = fmaf(x, wv.w, acc[r].w);
            }
        }
        #pragma unroll
        for (int r = 0; r < TE; r++)
            *(float4*)&g_Z[dir][t0 + r][j] = acc[r];
    }
}

// ============================================================================
// Kernel 2: sequential bidirectional LSTM recurrence — OUTPUT-SLICED.
// grid (4, 2), cluster (4,1,1): blockIdx.y = direction.
// CTA rank r owns h-outputs [r*40, min(r*40+40,150)) for ALL 4 gates.
// Per step: 4 gate dots per owned output (split-k, 2 thr/dot), CTA-local cell
// update, then each warp gathers its 4 h values via shfl and lane 0 pushes ONE
// st.async.v4 (16B) per peer: 30 tx/step instead of 114 scalar ones.
// ============================================================================
__global__ void __cluster_dims__(4, 1, 1) __launch_bounds__(320, 1)
lstm_rec_kernel(const float* __restrict__ Wr_f, const float* __restrict__ Wr_b)
{
    __shared__ __align__(16) float h_sh[2][KP];     // double-buffered hidden state
    __shared__ __align__(16) float a_sh[SLICE * 4]; // activated gates [o][g]
    __shared__ __align__(8)  unsigned long long mbar_sh[2];

    const int tid  = threadIdx.x;
    const int wrp  = tid >> 5;
    const int lane = tid & 31;
    const int u    = tid >> 1;         // unit 0..159
    const int kh   = tid & 1;          // k-half: 0 -> k[0..75], 1 -> k[76..151]
    const int g    = u & 3;            // gate 0=i 1=f 2=g 3=o
    const int o    = u >> 2;           // local output 0..39
    const uint32_t rank = my_cluster_rank();
    const int obase = rank * SLICE;
    const int myo   = obase + o;       // global output index
    const bool unit_act = (myo < U);
    const bool lead  = unit_act && (kh == 0);
    const bool cellT = lead && (g == 0);
    const int dir = blockIdx.y;
    const float* __restrict__ Wr = dir ? Wr_b : Wr_f;
    const int col = unit_act ? (g * U + myo) : 0;
    const int npush = (rank == 3) ? 8 : 10;              // warps that push v4
    const uint32_t inbytes = (rank == 3) ? 480 : 448;    // incoming bytes/step

    if (tid < KP) { h_sh[0][tid] = 0.f; h_sh[1][tid] = 0.f; }
    if (tid == 0) {
        mbar_init(smem_u32(&mbar_sh[0]), 1);
        mbar_init(smem_u32(&mbar_sh[1]), 1);
    }

    // register-resident weights (my k-half of Wr column `col`), f32x2 packed
    unsigned long long w2[38];
    #pragma unroll
    for (int jj = 0; jj < 38; jj++) {
        const int k = kh * 76 + 2 * jj;
        float wa = 0.f, wb = 0.f;
        if (unit_act && k     < U) wa = Wr[k * NZ + col];
        if (unit_act && k + 1 < U) wb = Wr[(k + 1) * NZ + col];
        w2[jj] = pack2(wa, wb);
    }

    // per-warp push targets: peer h_sh[nb][obase + 4*wrp] + peer barrier
    uint32_t pdst[2][3], pbar[2][3];
    {
        const uint32_t l0 = smem_u32(&h_sh[0][obase + 4 * wrp]);
        const uint32_t l1 = smem_u32(&h_sh[1][obase + 4 * wrp]);
        const uint32_t b0 = smem_u32(&mbar_sh[0]);
        const uint32_t b1 = smem_u32(&mbar_sh[1]);
        int n = 0;
        for (uint32_t r = 0; r < 4; r++) {
            if (r == rank) continue;
            pdst[0][n] = mapa_rank(l0, r);
            pdst[1][n] = mapa_rank(l1, r);
            pbar[0][n] = mapa_rank(b0, r);
            pbar[1][n] = mapa_rank(b1, r);
            n++;
        }
    }
    const uint32_t my_bar[2] = { smem_u32(&mbar_sh[0]), smem_u32(&mbar_sh[1]) };

    float c = 0.f;                 // cell state (cell threads only)
    int par[2] = { 0, 0 };         // phase parity per barrier
    __syncthreads();
    cluster_sync_();               // barriers + zeroed h live cluster-wide

    float zpre = lead ? __ldg(&g_Z[dir][dir ? (SEQ - 1) : 0][col]) : 0.f;

    for (int ti = 0; ti < SEQ; ti++) {
        const int t  = dir ? (SEQ - 1 - ti) : ti;
        const int b  = ti & 1;
        const int nb = b ^ 1;

        // wait for the 3 peer slices of this step's h (skip t=0: h=0)
        if (ti > 0) { mbar_wait_parity_cta(my_bar[b], par[b]); par[b] ^= 1; }
        // prime next step's barrier (counter math tolerates early stores)
        if (tid == 0 && ti + 1 < SEQ) mbar_arrive_expect_tx(my_bar[nb], inbytes);

        // z = zpre + (my k-half of h) . w    — dual accumulators
        unsigned long long a0 = pack2(zpre, 0.f), a1 = pack2(0.f, 0.f);
        const float4* h4 = (const float4*)&h_sh[b][kh * 76];
        #pragma unroll
        for (int j = 0; j < 19; j++) {
            const float4 hv = h4[j];
            fma2(a0, pack2(hv.x, hv.y), w2[2 * j + 0]);
            fma2(a1, pack2(hv.z, hv.w), w2[2 * j + 1]);
        }
        float f0, f1, f2, f3;
        unpack2(a0, f0, f1);
        unpack2(a1, f2, f3);
        float z = (f0 + f2) + (f1 + f3);
        z += __shfl_xor_sync(0xffffffffu, z, 1);    // combine k-halves

        if (lead) {
            const float a = (g == 2) ? tanh_approx(z) : sigmoid_fast(z);
            a_sh[o * 4 + g] = a;
        }
        __syncthreads();           // gates of my slice complete

        // prefetch next step's Z while exchange is in flight
        float zn = 0.f;
        if (lead && ti + 1 < SEQ)
            zn = __ldg(&g_Z[dir][dir ? (SEQ - 2 - ti) : (ti + 1)][col]);

        float hval = 0.f;          // pad lanes push 0.0 (tail stays zero)
        if (cellT) {
            const float4 av = *(const float4*)&a_sh[o * 4];   // i,f,g,o
            c = fmaf(av.y, c, av.x * av.z);
            hval = av.w * tanh_approx(c);
            h_sh[nb][myo] = hval;                 // own slice, local
            g_hidden[t][dir * U + myo] = hval;
        }

        // warp-gather the 4 cell h values (lanes 0,8,16,24) -> one v4 per peer
        if (wrp < npush && ti + 1 < SEQ) {
            const unsigned m = 0xffffffffu;
            const float vx = __shfl_sync(m, hval, 0);
            const float vy = __shfl_sync(m, hval, 8);
            const float vz = __shfl_sync(m, hval, 16);
            const float vw = __shfl_sync(m, hval, 24);
            if (lane == 0) {
                st_async_v4(pdst[nb][0], vx, vy, vz, vw, pbar[nb][0]);
                st_async_v4(pdst[nb][1], vx, vy, vz, vw, pbar[nb][1]);
                st_async_v4(pdst[nb][2], vx, vy, vz, vw, pbar[nb][2]);
            }
        }
        __syncthreads();           // own slice visible; a_sh reusable
        zpre = zn;
    }
    cluster_sync_();               // keep peers alive until traffic retired
}

// ============================================================================
// Kernel 3: out = hidden @ W1 + b1, TT=4 rows per block.
// ============================================================================
__global__ void __launch_bounds__(320) outGemm_kernel(
    const float* __restrict__ W1, const float* __restrict__ b1)
{
    __shared__ float hrow[TT][H1];
    const int t0 = blockIdx.x * TT;
    for (int i = threadIdx.x; i < TT * H1; i += 320)
        hrow[i / H1][i % H1] = g_hidden[t0 + i / H1][i % H1];
    __syncthreads();

    const int j = threadIdx.x;
    if (j < H1) {
        const float bj = b1[j];
        float acc[TT];
        #pragma unroll
        for (int r = 0; r < TT; r++) acc[r] = bj;
        #pragma unroll 4
        for (int d = 0; d < H1; d++) {
            const float w = __ldg(&W1[d * H1 + j]);
            #pragma unroll
            for (int r = 0; r < TT; r++) acc[r] = fmaf(hrow[r][d], w, acc[r]);
        }
        #pragma unroll
        for (int r = 0; r < TT; r++) g_out[t0 + r][j] = acc[r];
    }
}

// ============================================================================
// Kernel 4: per-position synonym attention + h_hat + c2, accumulate H.
// grid SEQ, block 128 (warp k handles synonym k).
// ============================================================================
__global__ void __launch_bounds__(128) syn_kernel(
    const int* __restrict__ sentence, const int* __restrict__ syn,
    const float* __restrict__ E,
    const float* __restrict__ W2, const float* __restrict__ b2)
{
    __shared__ float orow[H1];
    __shared__ float hhat[H1];
    __shared__ float e_sh[4][H1];
    __shared__ float coeff_sh[4];
    __shared__ float red_sh[4];
    __shared__ float c2_sh;

    const int s    = blockIdx.x;
    const int idx  = s ? (s - 1) : 0;
    const int tid  = threadIdx.x;
    const int wid  = tid >> 5;
    const int lane = tid & 31;

    for (int d = tid; d < H1; d += 128) {
        orow[d] = g_out[idx][d];
        hhat[d] = g_hidden[idx][d];
    }
    __syncthreads();

    {
        const int tok = sentence[s];
        const float* __restrict__ e = E + (size_t)syn[tok * 4 + wid] * D_IN;
        float p = 0.f;
        for (int d = lane; d < H1; d += 32) {
            const float ev = e[d];
            e_sh[wid][d] = ev;
            p = fmaf(ev, orow[d], p);
        }
        #pragma unroll
        for (int o = 16; o > 0; o >>= 1) p += __shfl_xor_sync(0xffffffffu, p, o);
        if (lane == 0) coeff_sh[wid] = __expf(p);
    }
    __syncthreads();

    const float c0 = coeff_sh[0], c1 = coeff_sh[1], c2c = coeff_sh[2], c3 = coeff_sh[3];
    for (int d = tid; d < H1; d += 128) {
        float v = hhat[d];
        v = fmaf(c0, e_sh[0][d], v);
        v = fmaf(c1, e_sh[1][d], v);
        v = fmaf(c2c, e_sh[2][d], v);
        v = fmaf(c3, e_sh[3][d], v);
        hhat[d] = v;
    }
    __syncthreads();

    float p = 0.f;
    for (int d = tid; d < H1; d += 128) p = fmaf(hhat[d], W2[d], p);
    #pragma unroll
    for (int o = 16; o > 0; o >>= 1) p += __shfl_xor_sync(0xffffffffu, p, o);
    if (lane == 0) red_sh[wid] = p;
    __syncthreads();
    if (tid == 0)
        c2_sh = __expf(tanhf(red_sh[0] + red_sh[1] + red_sh[2] + red_sh[3] + b2[0]));
    __syncthreads();

    const float c2 = c2_sh;
    for (int d = tid; d < H1; d += 128) atomicAdd(&g_H[d], c2 * hhat[d]);
}

// ============================================================================
// Kernel 5: heads — out[0..7] = H@We + be, out[8] = H@Ws + bs
// ============================================================================
__global__ void heads_kernel(
    const float* __restrict__ We, const float* __restrict__ be,
    const float* __restrict__ Ws, const float* __restrict__ bs,
    float* __restrict__ out)
{
    const int j = threadIdx.x;
    if (j < 8) {
        float acc = be[j];
        for (int d = 0; d < H1; d++) acc = fmaf(g_H[d], We[d * 8 + j], acc);
        out[j] = acc;
    } else if (j == 8) {
        float acc = bs[0];
        for (int d = 0; d < H1; d++) acc = fmaf(g_H[d], Ws[d], acc);
        out[8] = acc;
    }
}

// ============================================================================
extern "C" void kernel_launch(void* const* d_in, const int* in_sizes, int n_in,
                              void* d_out, int out_size)
{
    const int*   sentence = (const int*)  d_in[0];
    const int*   syn      = (const int*)  d_in[1];
    const float* E        = (const float*)d_in[2];
    const float* Wk_f     = (const float*)d_in[3];
    const float* Wr_f     = (const float*)d_in[4];
    const float* b_f      = (const float*)d_in[5];
    const float* Wk_b     = (const float*)d_in[6];
    const float* Wr_b     = (const float*)d_in[7];
    const float* b_b      = (const float*)d_in[8];
    const float* W1       = (const float*)d_in[9];
    const float* b1       = (const float*)d_in[10];
    const float* W2       = (const float*)d_in[11];
    const float* b2       = (const float*)d_in[12];
    const float* We       = (const float*)d_in[13];
    const float* be       = (const float*)d_in[14];
    const float* Ws       = (const float*)d_in[15];
    const float* bs       = (const float*)d_in[16];
    float* out = (float*)d_out;

    zeroH_kernel<<<1, 320>>>();
    embZ_kernel<<<dim3(SEQ / TE, 2), 160>>>(sentence, E, Wk_f, b_f, Wk_b, b_b);
    lstm_rec_kernel<<<dim3(4, 2), 320>>>(Wr_f, Wr_b);
    outGemm_kernel<<<SEQ / TT, 320>>>(W1, b1);
    syn_kernel<<<SEQ, 128>>>(sentence, syn, E, W2, b2);
    heads_kernel<<<1, 32>>>(We, be, Ws, bs, out);
}

// round 8
// speedup vs baseline: 1.4656x; 1.0263x over previous
#include <cuda_runtime.h>
#include <cuda_bf16.h>
#include <cstdint>

#define SEQ   2048
#define D_IN  300
#define U     150
#define NZ    600      // 4 gates * U
#define KP    152      // padded recurrence depth (multiple of 8)
#define H1    300
#define TE    8        // timestep tile for embZ
#define TT    4        // timestep tile for outGemm
#define SLICE 40       // h-outputs owned per CTA rank (rank3: 30 real + 2 pad)

// ------------------------- scratch (static device memory; no allocs) ---------
__device__ float g_Z[2][SEQ][NZ];        // precomputed x@Wk + b, per direction
__device__ float g_hidden[SEQ][H1];      // [hf | hb] concat
__device__ float g_out[SEQ][H1];         // hidden @ W1 + b1
__device__ float g_H[H1];                // final weighted sum

// ------------------------- small PTX helpers ---------------------------------
__device__ __forceinline__ uint32_t smem_u32(const void* p) {
    return (uint32_t)__cvta_generic_to_shared(p);
}
__device__ __forceinline__ uint32_t mapa_rank(uint32_t addr, uint32_t r) {
    uint32_t out;
    asm("mapa.shared::cluster.u32 %0, %1, %2;" : "=r"(out) : "r"(addr), "r"(r));
    return out;
}
__device__ __forceinline__ void cluster_sync_() {
    asm volatile("barrier.cluster.arrive.aligned;" ::: "memory");
    asm volatile("barrier.cluster.wait.aligned;" ::: "memory");
}
__device__ __forceinline__ uint32_t my_cluster_rank() {
    uint32_t r;
    asm("mov.u32 %0, %%cluster_ctarank;" : "=r"(r));
    return r;
}
__device__ __forceinline__ unsigned long long pack2(float lo, float hi) {
    unsigned long long r;
    asm("mov.b64 %0, {%1, %2};" : "=l"(r) : "f"(lo), "f"(hi));
    return r;
}
__device__ __forceinline__ void fma2(unsigned long long& d, unsigned long long a,
                                     unsigned long long b) {
    asm("fma.rn.f32x2 %0, %1, %2, %0;" : "+l"(d) : "l"(a), "l"(b));
}
__device__ __forceinline__ void unpack2(unsigned long long v, float& lo, float& hi) {
    asm("mov.b64 {%0, %1}, %2;" : "=f"(lo), "=f"(hi) : "l"(v));
}
__device__ __forceinline__ float tanh_approx(float x) {
    float r;
    asm("tanh.approx.f32 %0, %1;" : "=f"(r) : "f"(x));
    return r;
}
__device__ __forceinline__ float sigmoid_fast(float x) {
    float e;
    asm("ex2.approx.f32 %0, %1;" : "=f"(e) : "f"(-1.4426950408889634f * x));
    float r;
    asm("rcp.approx.f32 %0, %1;" : "=f"(r) : "f"(1.0f + e));
    return r;
}
__device__ __forceinline__ void mbar_init(uint32_t addr, uint32_t cnt) {
    asm volatile("mbarrier.init.shared.b64 [%0], %1;" :: "r"(addr), "r"(cnt) : "memory");
}
__device__ __forceinline__ void mbar_arrive_expect_tx(uint32_t addr, uint32_t tx) {
    asm volatile("mbarrier.arrive.expect_tx.shared.b64 _, [%0], %1;"
                 :: "r"(addr), "r"(tx) : "memory");
}
// CTA-scope acquire wait — st.async completion (complete_tx) provides the
// cross-CTA visibility; no cluster-scope fence -> no per-step L1D flush.
__device__ __forceinline__ void mbar_wait_parity_cta(uint32_t addr, uint32_t parity) {
    asm volatile(
        "{\n\t"
        ".reg .pred P1;\n\t"
        "WAIT_LOOP_%=:\n\t"
        "mbarrier.try_wait.parity.acquire.cta.shared::cta.b64 P1, [%0], %1, 0x989680;\n\t"
        "@P1 bra.uni WAIT_DONE_%=;\n\t"
        "bra.uni WAIT_LOOP_%=;\n\t"
        "WAIT_DONE_%=:\n\t"
        "}"
        :: "r"(addr), "r"(parity) : "memory");
}
// one 16-byte vector store, ONE complete_tx transaction at the target barrier
__device__ __forceinline__ void st_async_v4(uint32_t daddr, float x, float y,
                                            float z, float w, uint32_t mbar) {
    asm volatile(
        "st.async.shared::cluster.mbarrier::complete_tx::bytes.v4.b32 "
        "[%0], {%1, %2, %3, %4}, [%5];"
        :: "r"(daddr), "f"(x), "f"(y), "f"(z), "f"(w), "r"(mbar) : "memory");
}

// ============================================================================
// Kernel 0: zero the accumulator for H
// ============================================================================
__global__ void zeroH_kernel() {
    if (threadIdx.x < H1) g_H[threadIdx.x] = 0.f;
}

// ============================================================================
// Kernel 1: Z[dir][t][:] = x_t @ Wk + b, tiled over TE=8 timesteps.
// grid (SEQ/TE, 2), block 160.
// ============================================================================
__global__ void __launch_bounds__(160) embZ_kernel(
    const int* __restrict__ sentence, const float* __restrict__ E,
    const float* __restrict__ Wk_f, const float* __restrict__ b_f,
    const float* __restrict__ Wk_b, const float* __restrict__ b_b)
{
    __shared__ float x_sh[TE][D_IN];
    const int t0  = blockIdx.x * TE;
    const int dir = blockIdx.y;

    for (int i = threadIdx.x; i < TE * D_IN; i += 160) {
        const int r = i / D_IN, d = i % D_IN;
        x_sh[r][d] = E[(size_t)sentence[t0 + r] * D_IN + d];
    }
    __syncthreads();

    const float* __restrict__ Wk = dir ? Wk_b : Wk_f;
    const float* __restrict__ b  = dir ? b_b  : b_f;

    const int j = threadIdx.x * 4;
    if (j < NZ) {
        const float4 bv = *(const float4*)(b + j);
        float4 acc[TE];
        #pragma unroll
        for (int r = 0; r < TE; r++) acc[r] = bv;

        #pragma unroll 2
        for (int d = 0; d < D_IN; d++) {
            const float4 wv = *(const float4*)(Wk + d * NZ + j);
            #pragma unroll
            for (int r = 0; r < TE; r++) {
                const float x = x_sh[r][d];
                acc[r].x = fmaf(x, wv.x, acc[r].x);
                acc[r].y = fmaf(x, wv.y, acc[r].y);
                acc[r].z = fmaf(x, wv.z, acc[r].z);
                acc[r].w = fmaf(x, wv.w, acc[r].w);
            }
        }
        #pragma unroll
        for (int r = 0; r < TE; r++)
            *(float4*)&g_Z[dir][t0 + r][j] = acc[r];
    }
}

// ============================================================================
// Kernel 2: sequential bidirectional LSTM recurrence — OUTPUT-SLICED,
// SYNC-FREE inner loop.
// grid (4, 2), cluster (4,1,1): blockIdx.y = direction.
// CTA rank r owns h-outputs [r*40, r*40+40) (rank3: 30 real + pads) for ALL
// 4 gates. An output's 4 gate leads live in one 8-lane group, so the cell
// update uses shfl (no smem staging). h is delivered to all 4 CTAs
// (INCLUDING self) via st.async.v4 + double-buffered mbarrier: the barrier's
// tx count is the only synchronization — no __syncthreads in the loop.
// Safety: a peer can only overwrite my read-buffer after receiving all 608B
// for the next step, which includes my slowest warp's push, which postdates
// that warp's reads of the buffer.
// ============================================================================
__global__ void __cluster_dims__(4, 1, 1) __launch_bounds__(320, 1)
lstm_rec_kernel(const float* __restrict__ Wr_f, const float* __restrict__ Wr_b)
{
    __shared__ __align__(16) float h_sh[2][KP];     // double-buffered hidden state
    __shared__ __align__(8)  unsigned long long mbar_sh[2];

    const int tid  = threadIdx.x;
    const int wrp  = tid >> 5;
    const int lane = tid & 31;
    const int u    = tid >> 1;         // unit 0..159
    const int kh   = tid & 1;          // k-half: 0 -> k[0..75], 1 -> k[76..151]
    const int g    = u & 3;            // gate 0=i 1=f 2=g 3=o
    const int o    = u >> 2;           // local output 0..39
    const uint32_t rank = my_cluster_rank();
    const int obase = rank * SLICE;
    const int myo   = obase + o;       // global output index
    const bool unit_act = (myo < U);
    const bool lead  = unit_act && (kh == 0);
    const bool cellT = lead && (g == 0);
    const int dir = blockIdx.y;
    const float* __restrict__ Wr = dir ? Wr_b : Wr_f;
    const int col = unit_act ? (g * U + myo) : 0;
    const int npush = (rank == 3) ? 8 : 10;        // warps that push (rank3 pads to 152)
    const uint32_t inbytes = KP * 4;               // 608B: all 4 ranks incl. self

    if (tid < KP) { h_sh[0][tid] = 0.f; h_sh[1][tid] = 0.f; }
    if (tid == 0) {
        mbar_init(smem_u32(&mbar_sh[0]), 1);
        mbar_init(smem_u32(&mbar_sh[1]), 1);
    }

    // register-resident weights (my k-half of Wr column `col`), f32x2 packed
    unsigned long long w2[38];
    #pragma unroll
    for (int jj = 0; jj < 38; jj++) {
        const int k = kh * 76 + 2 * jj;
        float wa = 0.f, wb = 0.f;
        if (unit_act && k     < U) wa = Wr[k * NZ + col];
        if (unit_act && k + 1 < U) wb = Wr[(k + 1) * NZ + col];
        w2[jj] = pack2(wa, wb);
    }

    // per-warp push targets: slice slot + barrier in ALL 4 CTAs (incl. self)
    uint32_t pdst[2][4], pbar[2][4];
    {
        const uint32_t l0 = smem_u32(&h_sh[0][obase + 4 * wrp]);
        const uint32_t l1 = smem_u32(&h_sh[1][obase + 4 * wrp]);
        const uint32_t b0 = smem_u32(&mbar_sh[0]);
        const uint32_t b1 = smem_u32(&mbar_sh[1]);
        #pragma unroll
        for (uint32_t r = 0; r < 4; r++) {
            pdst[0][r] = mapa_rank(l0, r);
            pdst[1][r] = mapa_rank(l1, r);
            pbar[0][r] = mapa_rank(b0, r);
            pbar[1][r] = mapa_rank(b1, r);
        }
    }
    const uint32_t my_bar[2] = { smem_u32(&mbar_sh[0]), smem_u32(&mbar_sh[1]) };

    float c = 0.f;                 // cell state (cell threads only)
    int par[2] = { 0, 0 };         // phase parity per barrier
    __syncthreads();
    cluster_sync_();               // barriers + zeroed h live cluster-wide

    float zpre = lead ? __ldg(&g_Z[dir][dir ? (SEQ - 1) : 0][col]) : 0.f;
    const int lbase = lane & 24;   // base lane of my 8-lane output group

    for (int ti = 0; ti < SEQ; ti++) {
        const int t  = dir ? (SEQ - 1 - ti) : ti;
        const int b  = ti & 1;
        const int nb = b ^ 1;

        // the ONLY sync: wait for all 608B of this step's h (skip t=0: h=0)
        if (ti > 0) { mbar_wait_parity_cta(my_bar[b], par[b]); par[b] ^= 1; }
        // arm next buffer's barrier (tx counter tolerates early stores)
        if (tid == 0 && ti + 1 < SEQ) mbar_arrive_expect_tx(my_bar[nb], inbytes);

        // prefetch next step's Z (consumed next iteration -> latency hidden)
        float zn = 0.f;
        if (lead && ti + 1 < SEQ)
            zn = __ldg(&g_Z[dir][dir ? (SEQ - 2 - ti) : (ti + 1)][col]);

        // z = zpre + (my k-half of h) . w — u64 loads feed f32x2 FMA directly
        unsigned long long a0 = pack2(zpre, 0.f), a1 = pack2(0.f, 0.f);
        const ulonglong2* hp = (const ulonglong2*)&h_sh[b][kh * 76];
        #pragma unroll
        for (int j = 0; j < 19; j++) {
            const ulonglong2 hv = hp[j];
            fma2(a0, hv.x, w2[2 * j + 0]);
            fma2(a1, hv.y, w2[2 * j + 1]);
        }
        float f0, f1, f2, f3;
        unpack2(a0, f0, f1);
        unpack2(a1, f2, f3);
        float z = (f0 + f2) + (f1 + f3);
        z += __shfl_xor_sync(0xffffffffu, z, 1);    // combine k-halves

        // activation (every thread; leads hold the real value)
        const float a = (g == 2) ? tanh_approx(z) : sigmoid_fast(z);

        // intra-warp gate exchange: gates of output o sit at lanes lbase+2g
        const unsigned m = 0xffffffffu;
        const float af = __shfl_sync(m, a, lbase + 2);
        const float ag = __shfl_sync(m, a, lbase + 4);
        const float ao = __shfl_sync(m, a, lbase + 6);

        float hval = 0.f;          // pad lanes push 0.0 (tail stays zero)
        if (cellT) {               // a == input gate here
            c = fmaf(af, c, a * ag);
            hval = ao * tanh_approx(c);
            g_hidden[t][dir * U + myo] = hval;
        }

        // warp-gather the 4 cell h values (lanes 0,8,16,24) -> one v4 per CTA
        if (wrp < npush && ti + 1 < SEQ) {
            const float vx = __shfl_sync(m, hval, 0);
            const float vy = __shfl_sync(m, hval, 8);
            const float vz = __shfl_sync(m, hval, 16);
            const float vw = __shfl_sync(m, hval, 24);
            if (lane == 0) {
                st_async_v4(pdst[nb][0], vx, vy, vz, vw, pbar[nb][0]);
                st_async_v4(pdst[nb][1], vx, vy, vz, vw, pbar[nb][1]);
                st_async_v4(pdst[nb][2], vx, vy, vz, vw, pbar[nb][2]);
                st_async_v4(pdst[nb][3], vx, vy, vz, vw, pbar[nb][3]);
            }
        }
        zpre = zn;
    }
    cluster_sync_();               // keep peers alive until traffic retired
}

// ============================================================================
// Kernel 3: out = hidden @ W1 + b1, TT=4 rows per block.
// ============================================================================
__global__ void __launch_bounds__(320) outGemm_kernel(
    const float* __restrict__ W1, const float* __restrict__ b1)
{
    __shared__ float hrow[TT][H1];
    const int t0 = blockIdx.x * TT;
    for (int i = threadIdx.x; i < TT * H1; i += 320)
        hrow[i / H1][i % H1] = g_hidden[t0 + i / H1][i % H1];
    __syncthreads();

    const int j = threadIdx.x;
    if (j < H1) {
        const float bj = b1[j];
        float acc[TT];
        #pragma unroll
        for (int r = 0; r < TT; r++) acc[r] = bj;
        #pragma unroll 4
        for (int d = 0; d < H1; d++) {
            const float w = __ldg(&W1[d * H1 + j]);
            #pragma unroll
            for (int r = 0; r < TT; r++) acc[r] = fmaf(hrow[r][d], w, acc[r]);
        }
        #pragma unroll
        for (int r = 0; r < TT; r++) g_out[t0 + r][j] = acc[r];
    }
}

// ============================================================================
// Kernel 4: per-position synonym attention + h_hat + c2, accumulate H.
// grid SEQ, block 128 (warp k handles synonym k).
// ============================================================================
__global__ void __launch_bounds__(128) syn_kernel(
    const int* __restrict__ sentence, const int* __restrict__ syn,
    const float* __restrict__ E,
    const float* __restrict__ W2, const float* __restrict__ b2)
{
    __shared__ float orow[H1];
    __shared__ float hhat[H1];
    __shared__ float e_sh[4][H1];
    __shared__ float coeff_sh[4];
    __shared__ float red_sh[4];
    __shared__ float c2_sh;

    const int s    = blockIdx.x;
    const int idx  = s ? (s - 1) : 0;
    const int tid  = threadIdx.x;
    const int wid  = tid >> 5;
    const int lane = tid & 31;

    for (int d = tid; d < H1; d += 128) {
        orow[d] = g_out[idx][d];
        hhat[d] = g_hidden[idx][d];
    }
    __syncthreads();

    {
        const int tok = sentence[s];
        const float* __restrict__ e = E + (size_t)syn[tok * 4 + wid] * D_IN;
        float p = 0.f;
        for (int d = lane; d < H1; d += 32) {
            const float ev = e[d];
            e_sh[wid][d] = ev;
            p = fmaf(ev, orow[d], p);
        }
        #pragma unroll
        for (int o = 16; o > 0; o >>= 1) p += __shfl_xor_sync(0xffffffffu, p, o);
        if (lane == 0) coeff_sh[wid] = __expf(p);
    }
    __syncthreads();

    const float c0 = coeff_sh[0], c1 = coeff_sh[1], c2c = coeff_sh[2], c3 = coeff_sh[3];
    for (int d = tid; d < H1; d += 128) {
        float v = hhat[d];
        v = fmaf(c0, e_sh[0][d], v);
        v = fmaf(c1, e_sh[1][d], v);
        v = fmaf(c2c, e_sh[2][d], v);
        v = fmaf(c3, e_sh[3][d], v);
        hhat[d] = v;
    }
    __syncthreads();

    float p = 0.f;
    for (int d = tid; d < H1; d += 128) p = fmaf(hhat[d], W2[d], p);
    #pragma unroll
    for (int o = 16; o > 0; o >>= 1) p += __shfl_xor_sync(0xffffffffu, p, o);
    if (lane == 0) red_sh[wid] = p;
    __syncthreads();
    if (tid == 0)
        c2_sh = __expf(tanhf(red_sh[0] + red_sh[1] + red_sh[2] + red_sh[3] + b2[0]));
    __syncthreads();

    const float c2 = c2_sh;
    for (int d = tid; d < H1; d += 128) atomicAdd(&g_H[d], c2 * hhat[d]);
}

// ============================================================================
// Kernel 5: heads — out[0..7] = H@We + be, out[8] = H@Ws + bs
// ============================================================================
__global__ void heads_kernel(
    const float* __restrict__ We, const float* __restrict__ be,
    const float* __restrict__ Ws, const float* __restrict__ bs,
    float* __restrict__ out)
{
    const int j = threadIdx.x;
    if (j < 8) {
        float acc = be[j];
        for (int d = 0; d < H1; d++) acc = fmaf(g_H[d], We[d * 8 + j], acc);
        out[j] = acc;
    } else if (j == 8) {
        float acc = bs[0];
        for (int d = 0; d < H1; d++) acc = fmaf(g_H[d], Ws[d], acc);
        out[8] = acc;
    }
}

// ============================================================================
extern "C" void kernel_launch(void* const* d_in, const int* in_sizes, int n_in,
                              void* d_out, int out_size)
{
    const int*   sentence = (const int*)  d_in[0];
    const int*   syn      = (const int*)  d_in[1];
    const float* E        = (const float*)d_in[2];
    const float* Wk_f     = (const float*)d_in[3];
    const float* Wr_f     = (const float*)d_in[4];
    const float* b_f      = (const float*)d_in[5];
    const float* Wk_b     = (const float*)d_in[6];
    const float* Wr_b     = (const float*)d_in[7];
    const float* b_b      = (const float*)d_in[8];
    const float* W1       = (const float*)d_in[9];
    const float* b1       = (const float*)d_in[10];
    const float* W2       = (const float*)d_in[11];
    const float* b2       = (const float*)d_in[12];
    const float* We       = (const float*)d_in[13];
    const float* be       = (const float*)d_in[14];
    const float* Ws       = (const float*)d_in[15];
    const float* bs       = (const float*)d_in[16];
    float* out = (float*)d_out;

    zeroH_kernel<<<1, 320>>>();
    embZ_kernel<<<dim3(SEQ / TE, 2), 160>>>(sentence, E, Wk_f, b_f, Wk_b, b_b);
    lstm_rec_kernel<<<dim3(4, 2), 320>>>(Wr_f, Wr_b);
    outGemm_kernel<<<SEQ / TT, 320>>>(W1, b1);
    syn_kernel<<<SEQ, 128>>>(sentence, syn, E, W2, b2);
    heads_kernel<<<1, 32>>>(We, be, Ws, bs, out);
}

// round 10
// speedup vs baseline: 1.5435x; 1.0532x over previous
#include <cuda_runtime.h>
#include <cuda_bf16.h>
#include <cstdint>

#define SEQ   2048
#define D_IN  300
#define U     150
#define NZ    600      // 4 gates * U
#define H1    300
#define TE    8        // timestep tile for embZ
#define TT    2        // timestep tile for outGemm
#define NCTA  8        // cluster size (CTAs per direction); 8 = portable max
#define SLICE 20       // h-outputs owned per CTA rank (rank7: 10 real + 10 pad)
#define KP    160      // padded recurrence depth = NCTA*SLICE
#define KH    80       // split-k half depth
#define W2N   40       // f32x2 weights per thread (KH/2)

// ------------------------- scratch (static device memory; no allocs) ---------
__device__ float g_Z[2][SEQ][NZ];        // precomputed x@Wk + b, per direction
__device__ float g_hidden[SEQ][H1];      // [hf | hb] concat
__device__ float g_out[SEQ][H1];         // hidden @ W1 + b1
__device__ float g_H[H1];                // final weighted sum

// ------------------------- small PTX helpers ---------------------------------
__device__ __forceinline__ uint32_t smem_u32(const void* p) {
    return (uint32_t)__cvta_generic_to_shared(p);
}
__device__ __forceinline__ uint32_t mapa_rank(uint32_t addr, uint32_t r) {
    uint32_t out;
    asm("mapa.shared::cluster.u32 %0, %1, %2;" : "=r"(out) : "r"(addr), "r"(r));
    return out;
}
__device__ __forceinline__ void cluster_sync_() {
    asm volatile("barrier.cluster.arrive.aligned;" ::: "memory");
    asm volatile("barrier.cluster.wait.aligned;" ::: "memory");
}
__device__ __forceinline__ uint32_t my_cluster_rank() {
    uint32_t r;
    asm("mov.u32 %0, %%cluster_ctarank;" : "=r"(r));
    return r;
}
__device__ __forceinline__ unsigned long long pack2(float lo, float hi) {
    unsigned long long r;
    asm("mov.b64 %0, {%1, %2};" : "=l"(r) : "f"(lo), "f"(hi));
    return r;
}
__device__ __forceinline__ void fma2(unsigned long long& d, unsigned long long a,
                                     unsigned long long b) {
    asm("fma.rn.f32x2 %0, %1, %2, %0;" : "+l"(d) : "l"(a), "l"(b));
}
__device__ __forceinline__ void unpack2(unsigned long long v, float& lo, float& hi) {
    asm("mov.b64 {%0, %1}, %2;" : "=f"(lo), "=f"(hi) : "l"(v));
}
__device__ __forceinline__ float tanh_approx(float x) {
    float r;
    asm("tanh.approx.f32 %0, %1;" : "=f"(r) : "f"(x));
    return r;
}
__device__ __forceinline__ float sigmoid_fast(float x) {
    float e;
    asm("ex2.approx.f32 %0, %1;" : "=f"(e) : "f"(-1.4426950408889634f * x));
    float r;
    asm("rcp.approx.f32 %0, %1;" : "=f"(r) : "f"(1.0f + e));
    return r;
}
__device__ __forceinline__ void mbar_init(uint32_t addr, uint32_t cnt) {
    asm volatile("mbarrier.init.shared.b64 [%0], %1;" :: "r"(addr), "r"(cnt) : "memory");
}
__device__ __forceinline__ void mbar_arrive_expect_tx(uint32_t addr, uint32_t tx) {
    asm volatile("mbarrier.arrive.expect_tx.shared.b64 _, [%0], %1;"
                 :: "r"(addr), "r"(tx) : "memory");
}
// CTA-scope acquire wait — st.async completion (complete_tx) provides the
// cross-CTA visibility; no cluster-scope fence -> no per-step L1D flush.
__device__ __forceinline__ void mbar_wait_parity_cta(uint32_t addr, uint32_t parity) {
    asm volatile(
        "{\n\t"
        ".reg .pred P1;\n\t"
        "WAIT_LOOP_%=:\n\t"
        "mbarrier.try_wait.parity.acquire.cta.shared::cta.b64 P1, [%0], %1, 0x989680;\n\t"
        "@P1 bra.uni WAIT_DONE_%=;\n\t"
        "bra.uni WAIT_LOOP_%=;\n\t"
        "WAIT_DONE_%=:\n\t"
        "}"
        :: "r"(addr), "r"(parity) : "memory");
}
// one 16-byte vector store, ONE complete_tx transaction at the target barrier
__device__ __forceinline__ void st_async_v4(uint32_t daddr, float x, float y,
                                            float z, float w, uint32_t mbar) {
    asm volatile(
        "st.async.shared::cluster.mbarrier::complete_tx::bytes.v4.b32 "
        "[%0], {%1, %2, %3, %4}, [%5];"
        :: "r"(daddr), "f"(x), "f"(y), "f"(z), "f"(w), "r"(mbar) : "memory");
}

// ============================================================================
// Kernel 0: zero the accumulator for H
// ============================================================================
__global__ void zeroH_kernel() {
    if (threadIdx.x < H1) g_H[threadIdx.x] = 0.f;
}

// ============================================================================
// Kernel 1: Z[dir][t][:] = x_t @ Wk + b, tiled over TE=8 timesteps.
// grid (SEQ/TE, 2), block 160.
// ============================================================================
__global__ void __launch_bounds__(160) embZ_kernel(
    const int* __restrict__ sentence, const float* __restrict__ E,
    const float* __restrict__ Wk_f, const float* __restrict__ b_f,
    const float* __restrict__ Wk_b, const float* __restrict__ b_b)
{
    __shared__ float x_sh[TE][D_IN];
    const int t0  = blockIdx.x * TE;
    const int dir = blockIdx.y;

    for (int i = threadIdx.x; i < TE * D_IN; i += 160) {
        const int r = i / D_IN, d = i % D_IN;
        x_sh[r][d] = E[(size_t)sentence[t0 + r] * D_IN + d];
    }
    __syncthreads();

    const float* __restrict__ Wk = dir ? Wk_b : Wk_f;
    const float* __restrict__ b  = dir ? b_b  : b_f;

    const int j = threadIdx.x * 4;
    if (j < NZ) {
        const float4 bv = *(const float4*)(b + j);
        float4 acc[TE];
        #pragma unroll
        for (int r = 0; r < TE; r++) acc[r] = bv;

        #pragma unroll 2
        for (int d = 0; d < D_IN; d++) {
            const float4 wv = *(const float4*)(Wk + d * NZ + j);
            #pragma unroll
            for (int r = 0; r < TE; r++) {
                const float x = x_sh[r][d];
                acc[r].x = fmaf(x, wv.x, acc[r].x);
                acc[r].y = fmaf(x, wv.y, acc[r].y);
                acc[r].z = fmaf(x, wv.z, acc[r].z);
                acc[r].w = fmaf(x, wv.w, acc[r].w);
            }
        }
        #pragma unroll
        for (int r = 0; r < TE; r++)
            *(float4*)&g_Z[dir][t0 + r][j] = acc[r];
    }
}

// ============================================================================
// Kernel 2: sequential bidirectional LSTM recurrence — OUTPUT-SLICED over an
// 8-CTA cluster, SYNC-FREE inner loop.
// grid (8, 2), cluster (8,1,1): blockIdx.y = direction.
// CTA rank r owns h-outputs [r*20, r*20+20) (rank7: 10 real + 10 pad) for ALL
// 4 gates: 160 threads = 20 outputs x 4 gates x 2 split-k halves -> 5 warps
// per SM (worst SMSP has 2), lstm spread over 16 SMs. Gate exchange via
// intra-warp shfl; h delivered to all 8 CTAs (incl. self) via st.async.v4 +
// double-buffered mbarrier (tx count = the only synchronization). Fan-out 8
// split across lane0 (ranks 0-3) and lane16 (ranks 4-7).
// Reuse safety: a peer can only overwrite my read-buffer after receiving all
// 640B for the next step, which includes my slowest warp's push, which
// postdates that warp's reads of the buffer.
// ============================================================================
__global__ void __cluster_dims__(NCTA, 1, 1) __launch_bounds__(160, 1)
lstm_rec_kernel(const float* __restrict__ Wr_f, const float* __restrict__ Wr_b)
{
    __shared__ __align__(16) float h_sh[2][KP];     // double-buffered hidden state
    __shared__ __align__(8)  unsigned long long mbar_sh[2];

    const int tid  = threadIdx.x;
    const int wrp  = tid >> 5;
    const int lane = tid & 31;
    const int u    = tid >> 1;         // unit 0..79
    const int kh   = tid & 1;          // k-half: 0 -> k[0..79], 1 -> k[80..159]
    const int g    = u & 3;            // gate 0=i 1=f 2=g 3=o
    const int o    = u >> 2;           // local output 0..19
    const uint32_t rank = my_cluster_rank();
    const int obase = rank * SLICE;
    const int myo   = obase + o;       // global output index
    const bool unit_act = (myo < U);
    const bool lead  = unit_act && (kh == 0);
    const bool cellT = lead && (g == 0);
    const int dir = blockIdx.y;
    const float* __restrict__ Wr = dir ? Wr_b : Wr_f;
    const int col = unit_act ? (g * U + myo) : 0;
    const uint32_t inbytes = KP * 4;   // 640B: all 8 ranks incl. self

    if (tid < KP) { h_sh[0][tid] = 0.f; h_sh[1][tid] = 0.f; }
    if (tid == 0) {
        mbar_init(smem_u32(&mbar_sh[0]), 1);
        mbar_init(smem_u32(&mbar_sh[1]), 1);
    }

    // register-resident weights (my k-half of Wr column `col`), f32x2 packed
    unsigned long long w2[W2N];
    #pragma unroll
    for (int jj = 0; jj < W2N; jj++) {
        const int k = kh * KH + 2 * jj;
        float wa = 0.f, wb = 0.f;
        if (unit_act && k     < U) wa = Wr[k * NZ + col];
        if (unit_act && k + 1 < U) wb = Wr[(k + 1) * NZ + col];
        w2[jj] = pack2(wa, wb);
    }

    // push targets: lane0 covers ranks 0-3, lane16 covers ranks 4-7.
    const uint32_t rbase = (lane >= 16) ? 4u : 0u;
    uint32_t pdst[2][4], pbar[2][4];
    {
        const uint32_t l0 = smem_u32(&h_sh[0][obase + 4 * wrp]);
        const uint32_t l1 = smem_u32(&h_sh[1][obase + 4 * wrp]);
        const uint32_t b0 = smem_u32(&mbar_sh[0]);
        const uint32_t b1 = smem_u32(&mbar_sh[1]);
        #pragma unroll
        for (uint32_t i = 0; i < 4; i++) {
            pdst[0][i] = mapa_rank(l0, rbase + i);
            pdst[1][i] = mapa_rank(l1, rbase + i);
            pbar[0][i] = mapa_rank(b0, rbase + i);
            pbar[1][i] = mapa_rank(b1, rbase + i);
        }
    }
    const uint32_t my_bar[2] = { smem_u32(&mbar_sh[0]), smem_u32(&mbar_sh[1]) };

    float c = 0.f;                 // cell state (cell threads only)
    int par[2] = { 0, 0 };         // phase parity per barrier
    __syncthreads();
    cluster_sync_();               // barriers + zeroed h live cluster-wide

    float zpre = lead ? __ldg(&g_Z[dir][dir ? (SEQ - 1) : 0][col]) : 0.f;
    const int lbase = lane & 24;   // base lane of my 8-lane output group

    for (int ti = 0; ti < SEQ; ti++) {
        const int t  = dir ? (SEQ - 1 - ti) : ti;
        const int b  = ti & 1;
        const int nb = b ^ 1;

        // the ONLY sync: wait for all 640B of this step's h (skip t=0: h=0)
        if (ti > 0) { mbar_wait_parity_cta(my_bar[b], par[b]); par[b] ^= 1; }
        // arm next buffer's barrier (tx counter tolerates early stores)
        if (tid == 0 && ti + 1 < SEQ) mbar_arrive_expect_tx(my_bar[nb], inbytes);

        // prefetch next step's Z (consumed next iteration -> latency hidden)
        float zn = 0.f;
        if (lead && ti + 1 < SEQ)
            zn = __ldg(&g_Z[dir][dir ? (SEQ - 2 - ti) : (ti + 1)][col]);

        // z = zpre + (my k-half of h) . w — u64 loads feed f32x2 FMA directly
        unsigned long long a0 = pack2(zpre, 0.f), a1 = pack2(0.f, 0.f);
        const ulonglong2* hp = (const ulonglong2*)&h_sh[b][kh * KH];
        #pragma unroll
        for (int j = 0; j < W2N / 2; j++) {
            const ulonglong2 hv = hp[j];
            fma2(a0, hv.x, w2[2 * j + 0]);
            fma2(a1, hv.y, w2[2 * j + 1]);
        }
        float f0, f1, f2, f3;
        unpack2(a0, f0, f1);
        unpack2(a1, f2, f3);
        float z = (f0 + f2) + (f1 + f3);
        z += __shfl_xor_sync(0xffffffffu, z, 1);    // combine k-halves

        // activation (every thread; leads hold the real value)
        const float a = (g == 2) ? tanh_approx(z) : sigmoid_fast(z);

        // intra-warp gate exchange: gates of output o sit at lanes lbase+2g
        const unsigned m = 0xffffffffu;
        const float af = __shfl_sync(m, a, lbase + 2);
        const float ag = __shfl_sync(m, a, lbase + 4);
        const float ao = __shfl_sync(m, a, lbase + 6);

        float hval = 0.f;          // pad lanes push 0.0 (tail stays zero)
        float cnew = c;
        if (cellT) {               // a == input gate here
            cnew = fmaf(af, c, a * ag);
            hval = ao * tanh_approx(cnew);
        }
        c = cnew;

        // warp-gather the 4 cell h values (lanes 0,8,16,24); push FIRST
        // (critical path), then the global store for downstream kernels.
        if (ti + 1 < SEQ) {
            const float vx = __shfl_sync(m, hval, 0);
            const float vy = __shfl_sync(m, hval, 8);
            const float vz = __shfl_sync(m, hval, 16);
            const float vw = __shfl_sync(m, hval, 24);
            if ((lane & 15) == 0) {
                st_async_v4(pdst[nb][0], vx, vy, vz, vw, pbar[nb][0]);
                st_async_v4(pdst[nb][1], vx, vy, vz, vw, pbar[nb][1]);
                st_async_v4(pdst[nb][2], vx, vy, vz, vw, pbar[nb][2]);
                st_async_v4(pdst[nb][3], vx, vy, vz, vw, pbar[nb][3]);
            }
        }
        if (cellT) g_hidden[t][dir * U + myo] = hval;
        zpre = zn;
    }
    cluster_sync_();               // keep peers alive until traffic retired
}

// ============================================================================
// Kernel 3: out = hidden @ W1 + b1, TT=2 rows per block (grid 1024).
// ============================================================================
__global__ void __launch_bounds__(320) outGemm_kernel(
    const float* __restrict__ W1, const float* __restrict__ b1)
{
    __shared__ float hrow[TT][H1];
    const int t0 = blockIdx.x * TT;
    for (int i = threadIdx.x; i < TT * H1; i += 320)
        hrow[i / H1][i % H1] = g_hidden[t0 + i / H1][i % H1];
    __syncthreads();

    const int j = threadIdx.x;
    if (j < H1) {
        const float bj = b1[j];
        float acc[TT];
        #pragma unroll
        for (int r = 0; r < TT; r++) acc[r] = bj;
        #pragma unroll 4
        for (int d = 0; d < H1; d++) {
            const float w = __ldg(&W1[d * H1 + j]);
            #pragma unroll
            for (int r = 0; r < TT; r++) acc[r] = fmaf(hrow[r][d], w, acc[r]);
        }
        #pragma unroll
        for (int r = 0; r < TT; r++) g_out[t0 + r][j] = acc[r];
    }
}

// ============================================================================
// Kernel 4: per-position synonym attention + h_hat + c2, accumulate H.
// grid SEQ, block 128 (warp k handles synonym k).
// ============================================================================
__global__ void __launch_bounds__(128) syn_kernel(
    const int* __restrict__ sentence, const int* __restrict__ syn,
    const float* __restrict__ E,
    const float* __restrict__ W2, const float* __restrict__ b2)
{
    __shared__ float orow[H1];
    __shared__ float hhat[H1];
    __shared__ float e_sh[4][H1];
    __shared__ float coeff_sh[4];
    __shared__ float red_sh[4];
    __shared__ float c2_sh;

    const int s    = blockIdx.x;
    const int idx  = s ? (s - 1) : 0;
    const int tid  = threadIdx.x;
    const int wid  = tid >> 5;
    const int lane = tid & 31;

    for (int d = tid; d < H1; d += 128) {
        orow[d] = g_out[idx][d];
        hhat[d] = g_hidden[idx][d];
    }
    __syncthreads();

    {
        const int tok = sentence[s];
        const float* __restrict__ e = E + (size_t)syn[tok * 4 + wid] * D_IN;
        float p = 0.f;
        for (int d = lane; d < H1; d += 32) {
            const float ev = e[d];
            e_sh[wid][d] = ev;
            p = fmaf(ev, orow[d], p);
        }
        #pragma unroll
        for (int o = 16; o > 0; o >>= 1) p += __shfl_xor_sync(0xffffffffu, p, o);
        if (lane == 0) coeff_sh[wid] = __expf(p);
    }
    __syncthreads();

    const float c0 = coeff_sh[0], c1 = coeff_sh[1], c2c = coeff_sh[2], c3 = coeff_sh[3];
    for (int d = tid; d < H1; d += 128) {
        float v = hhat[d];
        v = fmaf(c0, e_sh[0][d], v);
        v = fmaf(c1, e_sh[1][d], v);
        v = fmaf(c2c, e_sh[2][d], v);
        v = fmaf(c3, e_sh[3][d], v);
        hhat[d] = v;
    }
    __syncthreads();

    float p = 0.f;
    for (int d = tid; d < H1; d += 128) p = fmaf(hhat[d], W2[d], p);
    #pragma unroll
    for (int o = 16; o > 0; o >>= 1) p += __shfl_xor_sync(0xffffffffu, p, o);
    if (lane == 0) red_sh[wid] = p;
    __syncthreads();
    if (tid == 0)
        c2_sh = __expf(tanhf(red_sh[0] + red_sh[1] + red_sh[2] + red_sh[3] + b2[0]));
    __syncthreads();

    const float c2 = c2_sh;
    for (int d = tid; d < H1; d += 128) atomicAdd(&g_H[d], c2 * hhat[d]);
}

// ============================================================================
// Kernel 5: heads — out[0..7] = H@We + be, out[8] = H@Ws + bs
// ============================================================================
__global__ void heads_kernel(
    const float* __restrict__ We, const float* __restrict__ be,
    const float* __restrict__ Ws, const float* __restrict__ bs,
    float* __restrict__ out)
{
    const int j = threadIdx.x;
    if (j < 8) {
        float acc = be[j];
        for (int d = 0; d < H1; d++) acc = fmaf(g_H[d], We[d * 8 + j], acc);
        out[j] = acc;
    } else if (j == 8) {
        float acc = bs[0];
        for (int d = 0; d < H1; d++) acc = fmaf(g_H[d], Ws[d], acc);
        out[8] = acc;
    }
}

// ============================================================================
extern "C" void kernel_launch(void* const* d_in, const int* in_sizes, int n_in,
                              void* d_out, int out_size)
{
    const int*   sentence = (const int*)  d_in[0];
    const int*   syn      = (const int*)  d_in[1];
    const float* E        = (const float*)d_in[2];
    const float* Wk_f     = (const float*)d_in[3];
    const float* Wr_f     = (const float*)d_in[4];
    const float* b_f      = (const float*)d_in[5];
    const float* Wk_b     = (const float*)d_in[6];
    const float* Wr_b     = (const float*)d_in[7];
    const float* b_b      = (const float*)d_in[8];
    const float* W1       = (const float*)d_in[9];
    const float* b1       = (const float*)d_in[10];
    const float* W2       = (const float*)d_in[11];
    const float* b2       = (const float*)d_in[12];
    const float* We       = (const float*)d_in[13];
    const float* be       = (const float*)d_in[14];
    const float* Ws       = (const float*)d_in[15];
    const float* bs       = (const float*)d_in[16];
    float* out = (float*)d_out;

    zeroH_kernel<<<1, 320>>>();
    embZ_kernel<<<dim3(SEQ / TE, 2), 160>>>(sentence, E, Wk_f, b_f, Wk_b, b_b);
    lstm_rec_kernel<<<dim3(NCTA, 2), 160>>>(Wr_f, Wr_b);
    outGemm_kernel<<<SEQ / TT, 320>>>(W1, b1);
    syn_kernel<<<SEQ, 128>>>(sentence, syn, E, W2, b2);
    heads_kernel<<<1, 32>>>(We, be, Ws, bs, out);
}